// round 14
// baseline (speedup 1.0000x reference)
#include <cuda_runtime.h>
#include <math.h>

#define BB 32
#define CL 400
#define QL 30
#define HH 600
#define VOC 50000
#define EMB 300

#define LKS 6    // lstm k-split (kslice 100, padded to 112)
#define DKS 6    // decoder k-split (K=1200, kslice 200)
#define CKS 24   // comb k-split (K=1800, kslice 75)

#define LSTM_BLOCKS 120   // 10 n-tiles x LKS x 2 dirs
#define LTHREADS 512      // 16 warps

#define WS_STRIDE 116
#define WS_FLOATS (256 * WS_STRIDE)   // 29696
#define XC_FLOATS (32 * 260)          // 8320
#define LSTM_SMEM_BYTES ((WS_FLOATS + XC_FLOATS) * 4)   // 152064

// ---------------- scratch (device globals; allocation-free) ----------------
__device__ float g_cemb[BB*CL*HH];
__device__ float g_qemb[BB*QL*HH];
__device__ float g_xwf [BB*CL*4*HH];        // plain gate-blocked x-parts [row][g*600+j]
__device__ float g_xwb [BB*CL*4*HH];
__device__ float g_qx  [BB*QL*4*HH];
__device__ float g_whd_t[HH*HH*4];          // [k][j*4+g]
__device__ float g_wxo_t[HH*HH*4];
__device__ float g_whf_nk[4*HH*HH];         // [n=j*4+g][k]
__device__ float g_whb_nk[4*HH*HH];
__device__ float g_embt [HH*EMB];
__device__ float g_wxft [4*HH*HH];
__device__ float g_wxbt [4*HH*HH];
__device__ float g_wxdqt[4*HH*HH];
__device__ float g_watt [HH*2*HH];
__device__ float g_wgent[VOC*HH];
__device__ float g_enc [BB*CL*2*HH];
__device__ float g_encp[BB*CL*HH];
__device__ float g_stateH[2*2*BB*HH];       // [dir][phase][b][j]
__device__ float g_stateC[2*BB*HH];
__device__ float g_hd[2][BB*HH];
__device__ float g_cd[BB*HH];
__device__ float g_oprev[BB*HH];
__device__ float g_alpha[BB*CL];
__device__ float g_a[BB*2*HH];
__device__ float g_outs[BB*QL*HH];
__device__ float g_lpart2[2*LKS*BB*4*HH];
__device__ float g_dpart[DKS*BB*4*HH];
__device__ float g_cpart[CKS*BB*HH];

// LSTM barrier: cnt and gen on separate 128B lines
__device__ __align__(128) unsigned g_lbar_cnt[32];
__device__ __align__(128) unsigned g_lbar_genw[32];

__device__ __forceinline__ void grid_sync_ptr(unsigned* cnt, volatile unsigned* gen, unsigned nb)
{
    __syncthreads();
    if (threadIdx.x == 0) {
        unsigned g = *gen;
        __threadfence();
        if (atomicAdd(cnt, 1u) == nb - 1u) {
            *cnt = 0u;
            __threadfence();
            *gen = g + 1u;
        } else {
            while (*gen == g) { }
            __threadfence();
        }
    }
    __syncthreads();
}

__device__ __forceinline__ float sigf(float x) { return 1.0f / (1.0f + expf(-x)); }

__device__ __forceinline__ float tf32r(float f)
{
    unsigned u; asm("cvt.rna.tf32.f32 %0, %1;" : "=r"(u) : "f"(f));
    return __uint_as_float(u);
}
__device__ __forceinline__ float4 tf32r4(float4 v)
{
    return make_float4(tf32r(v.x), tf32r(v.y), tf32r(v.z), tf32r(v.w));
}
__device__ __forceinline__ void mma8(float* d, const unsigned* a, const unsigned* b)
{
    asm volatile("mma.sync.aligned.m16n8k8.row.col.f32.tf32.tf32.f32 "
        "{%0,%1,%2,%3}, {%4,%5,%6,%7}, {%8,%9}, {%0,%1,%2,%3};"
        : "+f"(d[0]), "+f"(d[1]), "+f"(d[2]), "+f"(d[3])
        : "r"(a[0]), "r"(a[1]), "r"(a[2]), "r"(a[3]), "r"(b[0]), "r"(b[1]));
}

__device__ __forceinline__ unsigned smem_u32p(const void* p)
{
    return (unsigned)__cvta_generic_to_shared(p);
}
__device__ __forceinline__ void cpa16(unsigned dst, const void* src, int bytes)
{
    asm volatile("cp.async.cg.shared.global [%0], [%1], 16, %2;"
                 :: "r"(dst), "l"(src), "r"(bytes) : "memory");
}

// ---------------- tf32 GEMM v2: 128N x 64M, cp.async 2-stage (best measured) -
__global__ void gemm_tf32(const float* __restrict__ X, const int* __restrict__ gidx,
                          const float* __restrict__ Wt, const float* __restrict__ bias,
                          float* __restrict__ C, int M, int N, int K)
{
    __shared__ float smem[8448];    // WsB[2]:2x2560, XsB[2]:2x1280 (=7680); Cs overlay 8448
    float* WsB[2] = { smem, smem + 2560 };
    float* XsB[2] = { smem + 5120, smem + 6400 };
    const int tid = threadIdx.x;
    const int warp = tid >> 5, lane = tid & 31;
    const int lq = lane >> 2, lr = lane & 3;
    const int wn = (warp & 3) * 32, wm = (warp >> 2) * 32;
    const int bn0 = blockIdx.x * 128;
    const int bm0 = blockIdx.y * 64;

    const int kqw = (tid & 3) * 4;
    const int n_0 = tid >> 2;
    const int n_1 = (tid + 256) >> 2;
    const int m_x = tid >> 2;
    const float* rowW0 = (bn0 + n_0 < N) ? Wt + (long)(bn0 + n_0) * K : nullptr;
    const float* rowW1 = (bn0 + n_1 < N) ? Wt + (long)(bn0 + n_1) * K : nullptr;
    const float* rowX  = nullptr;
    if (bm0 + m_x < M)
        rowX = X + (gidx ? (long)gidx[bm0 + m_x] * K : (long)(bm0 + m_x) * K);

    unsigned wsa0[2], wsa1[2], xsa[2];
#pragma unroll
    for (int b = 0; b < 2; b++) {
        wsa0[b] = smem_u32p(&WsB[b][n_0 * 20 + kqw]);
        wsa1[b] = smem_u32p(&WsB[b][n_1 * 20 + kqw]);
        xsa[b]  = smem_u32p(&XsB[b][m_x * 20 + kqw]);
    }

    const int KT = (K + 15) / 16;

#define G_ISSUE(KT0, BUF) do {                                              \
        int kk_ = (KT0) * 16 + kqw;                                         \
        int in_ = (kk_ < K);                                                \
        int b0_ = (rowW0 && in_) ? 16 : 0;                                  \
        int b1_ = (rowW1 && in_) ? 16 : 0;                                  \
        int bx_ = (rowX  && in_) ? 16 : 0;                                  \
        cpa16(wsa0[BUF], b0_ ? rowW0 + kk_ : Wt, b0_);                      \
        cpa16(wsa1[BUF], b1_ ? rowW1 + kk_ : Wt, b1_);                      \
        cpa16(xsa[BUF],  bx_ ? rowX  + kk_ : Wt, bx_);                      \
        asm volatile("cp.async.commit_group;" ::: "memory");                \
    } while (0)

    float acc[2][4][4];
#pragma unroll
    for (int t = 0; t < 2; t++)
#pragma unroll
        for (int u = 0; u < 4; u++)
#pragma unroll
            for (int e = 0; e < 4; e++) acc[t][u][e] = 0.f;

    G_ISSUE(0, 0);
    for (int kt = 0; kt < KT; kt++) {
        if (kt + 1 < KT) {
            G_ISSUE(kt + 1, (kt + 1) & 1);
            asm volatile("cp.async.wait_group 1;" ::: "memory");
        } else {
            asm volatile("cp.async.wait_group 0;" ::: "memory");
        }
        __syncthreads();

        const float* Ws = WsB[kt & 1];
        const float* Xs = XsB[kt & 1];
#pragma unroll
        for (int kc = 0; kc < 2; kc++) {
            const int kb = kc * 8 + lr;
            unsigned a[2][4], b[4][2];
#pragma unroll
            for (int t = 0; t < 2; t++) {
                const float* p = Ws + (wn + t * 16 + lq) * 20 + kb;
                a[t][0] = __float_as_uint(p[0]);
                a[t][1] = __float_as_uint(p[8 * 20]);
                a[t][2] = __float_as_uint(p[4]);
                a[t][3] = __float_as_uint(p[8 * 20 + 4]);
            }
#pragma unroll
            for (int u = 0; u < 4; u++) {
                const float* p = Xs + (wm + u * 8 + lq) * 20 + kb;
                b[u][0] = __float_as_uint(p[0]);
                b[u][1] = __float_as_uint(p[4]);
            }
#pragma unroll
            for (int t = 0; t < 2; t++)
#pragma unroll
                for (int u = 0; u < 4; u++)
                    mma8(acc[t][u], a[t], b[u]);
        }
        __syncthreads();
    }
#undef G_ISSUE

    float* Cs = smem;
#pragma unroll
    for (int t = 0; t < 2; t++)
#pragma unroll
        for (int u = 0; u < 4; u++) {
            int nl = wn + t * 16 + lq;
            int m = wm + u * 8 + lr * 2;
            Cs[m * 132 + nl]           = acc[t][u][0];
            Cs[(m + 1) * 132 + nl]     = acc[t][u][1];
            Cs[m * 132 + nl + 8]       = acc[t][u][2];
            Cs[(m + 1) * 132 + nl + 8] = acc[t][u][3];
        }
    __syncthreads();
#pragma unroll
    for (int l = 0; l < 8; l++) {
        int idx = tid + l * 256;
        int m = idx >> 5, nl4 = (idx & 31) * 4;
        int gm = bm0 + m, gn = bn0 + nl4;
        if (gm < M && gn < N) {
            float4 v = *(float4*)&Cs[m * 132 + nl4];
            if (gn + 3 < N) {
                if (bias) {
                    v.x += bias[gn]; v.y += bias[gn + 1];
                    v.z += bias[gn + 2]; v.w += bias[gn + 3];
                }
                *(float4*)(C + (long)gm * N + gn) = v;
            } else {
                float vv[4] = {v.x, v.y, v.z, v.w};
                for (int e = 0; e < 4; e++)
                    if (gn + e < N)
                        C[(long)gm * N + gn + e] = vv[e] + (bias ? bias[gn + e] : 0.f);
            }
        }
    }
}

// ---------------- small helpers ----------------
__global__ void zero_state_kernel()
{
    int i = blockIdx.x * 256 + threadIdx.x;
    if (i < 2 * 2 * BB * HH) g_stateH[i] = 0.f;
    if (i < 2 * BB * HH)     g_stateC[i] = 0.f;
    if (i < 32) { g_lbar_cnt[i] = 0u; g_lbar_genw[i] = 0u; }
}

__global__ void transpose_gates(const float* __restrict__ W, float* __restrict__ Wt)
{
    int idx = blockIdx.x * 256 + threadIdx.x;
    if (idx >= HH * HH) return;
    int k = idx / HH, j = idx % HH;
    float4 v;
    v.x = W[k * 4 * HH + j];
    v.y = W[k * 4 * HH + HH + j];
    v.z = W[k * 4 * HH + 2 * HH + j];
    v.w = W[k * 4 * HH + 3 * HH + j];
    ((float4*)Wt)[idx] = v;
}

__global__ void transpose_gates_nk(const float* __restrict__ W, float* __restrict__ out)
{
    long idx = (long)blockIdx.x * 256 + threadIdx.x;
    if (idx >= (long)4 * HH * HH) return;
    int n = (int)(idx / HH), k = (int)(idx % HH);
    out[idx] = W[(long)k * 4 * HH + (n & 3) * HH + (n >> 2)];
}

__global__ void transpose_t(const float* __restrict__ in, float* __restrict__ out,
                            int K, int N, int ldin)
{
    __shared__ float t[32][33];
    int kb = blockIdx.y * 32, nb = blockIdx.x * 32;
    int x = threadIdx.x, y = threadIdx.y;
    for (int i = y; i < 32; i += 8)
        t[i][x] = (kb + i < K && nb + x < N) ? in[(long)(kb + i) * ldin + nb + x] : 0.f;
    __syncthreads();
    for (int i = y; i < 32; i += 8)
        if (nb + i < N && kb + x < K)
            out[(long)(nb + i) * K + kb + x] = t[x][i];
}

// ---------------- persistent BiLSTM: 512 threads, weights smem-resident -----
__global__ void lstm_persist(const float* __restrict__ Wf, const float* __restrict__ Wb,
                             const float* __restrict__ xf, const float* __restrict__ xb,
                             float* __restrict__ SH, float* __restrict__ SC,
                             float* __restrict__ enc, float* __restrict__ lpart,
                             unsigned* bcnt, unsigned* bgenw)
{
    extern __shared__ float dsm[];
    float* Ws = dsm;
    float* Xs = dsm + WS_FLOATS;
    float* Cs = dsm + WS_FLOATS;

    const int bx = blockIdx.x;
    const int tid = threadIdx.x;
    const int warp = tid >> 5, lane = tid & 31;
    const int lq = lane >> 2, lr = lane & 3;
    const int nb = bx % 10;
    const int ks = (bx / 10) % LKS;
    const int dir = bx / (10 * LKS);
    const int n0 = nb * 256;
    const int k0 = ks * 100;
    const int wn = warp * 16;
    const float* Wnk = dir ? Wb : Wf;
    float* outP = lpart + (long)(dir * LKS + ks) * BB * 4 * HH;
    volatile unsigned* bgen = (volatile unsigned*)bgenw;

    for (int idx4 = tid; idx4 < 256 * 29; idx4 += LTHREADS) {
        int n = idx4 / 29, kq = (idx4 % 29) * 4;
        float4 v = make_float4(0.f, 0.f, 0.f, 0.f);
        int gn = n0 + n;
        if (gn < 4 * HH && kq < 100)
            v = tf32r4(*(const float4*)(Wnk + (long)gn * HH + k0 + kq));
        *(float4*)&Ws[n * WS_STRIDE + kq] = v;
    }
    __syncthreads();

    for (int s = 0; s < CL; s++) {
        const int ph = s & 1;
        const float* H = SH + (long)(dir * 2 + ph) * BB * HH;

        for (int idx4 = tid; idx4 < 928; idx4 += LTHREADS) {
            int m = idx4 / 29, kq = (idx4 % 29) * 4;
            float4 v = make_float4(0.f, 0.f, 0.f, 0.f);
            if (kq < 100)
                v = tf32r4(*(const float4*)(H + (long)m * HH + k0 + kq));
            *(float4*)&Xs[m * WS_STRIDE + kq] = v;
        }
        __syncthreads();

        float acc[4][4];
#pragma unroll
        for (int u = 0; u < 4; u++)
#pragma unroll
            for (int e = 0; e < 4; e++) acc[u][e] = 0.f;

#pragma unroll
        for (int kt = 0; kt < 7; kt++) {
#pragma unroll
            for (int kc = 0; kc < 2; kc++) {
                const int kb = kt * 16 + kc * 8 + lr;
                unsigned a[4], b[4][2];
                const float* pa = Ws + (wn + lq) * WS_STRIDE + kb;
                a[0] = __float_as_uint(pa[0]);
                a[1] = __float_as_uint(pa[8 * WS_STRIDE]);
                a[2] = __float_as_uint(pa[4]);
                a[3] = __float_as_uint(pa[8 * WS_STRIDE + 4]);
#pragma unroll
                for (int u = 0; u < 4; u++) {
                    const float* pb = Xs + (u * 8 + lq) * WS_STRIDE + kb;
                    b[u][0] = __float_as_uint(pb[0]);
                    b[u][1] = __float_as_uint(pb[4]);
                }
#pragma unroll
                for (int u = 0; u < 4; u++)
                    mma8(acc[u], a, b[u]);
            }
        }
        __syncthreads();

#pragma unroll
        for (int u = 0; u < 4; u++) {
            int nl = wn + lq;
            int m = u * 8 + lr * 2;
            Cs[m * 260 + nl]           = acc[u][0];
            Cs[(m + 1) * 260 + nl]     = acc[u][1];
            Cs[m * 260 + nl + 8]       = acc[u][2];
            Cs[(m + 1) * 260 + nl + 8] = acc[u][3];
        }
        __syncthreads();
#pragma unroll
        for (int l = 0; l < 4; l++) {
            int idx = tid + l * LTHREADS;
            int m = idx >> 6, nl4 = (idx & 63) * 4;
            if (n0 + nl4 < 4 * HH)
                *(float4*)(outP + (long)m * 4 * HH + n0 + nl4) = *(float4*)&Cs[m * 260 + nl4];
        }
        grid_sync_ptr(bcnt, bgen, LSTM_BLOCKS);

        for (int idx = bx * LTHREADS + tid; idx < 2 * BB * HH; idx += LSTM_BLOCKS * LTHREADS) {
            const int d2 = idx / (BB * HH);
            const int r2 = idx % (BB * HH);
            const int b = r2 / HH, j = r2 % HH;
            const int tt = d2 ? (CL - 1 - s) : s;
            float4 g4 = make_float4(0.f, 0.f, 0.f, 0.f);
#pragma unroll
            for (int kq = 0; kq < LKS; kq++) {
                const float4* P = (const float4*)(lpart + ((long)(d2 * LKS + kq) * BB + b) * 4 * HH);
                float4 p = P[j];
                g4.x += p.x; g4.y += p.y; g4.z += p.z; g4.w += p.w;
            }
            const float* xw = d2 ? xb : xf;
            const long xbs = ((long)b * CL + tt) * 4 * HH;
            float gi = g4.x + xw[xbs + j];
            float gf = g4.y + xw[xbs + HH + j];
            float gg = g4.z + xw[xbs + 2 * HH + j];
            float go = g4.w + xw[xbs + 3 * HH + j];
            float c = SC[(long)d2 * BB * HH + b * HH + j];
            c = sigf(gf) * c + sigf(gi) * tanhf(gg);
            float h = sigf(go) * tanhf(c);
            SC[(long)d2 * BB * HH + b * HH + j] = c;
            SH[(long)(d2 * 2 + (ph ^ 1)) * BB * HH + b * HH + j] = h;
            enc[((long)b * CL + tt) * 2 * HH + d2 * HH + j] = h;
        }
        grid_sync_ptr(bcnt, bgen, LSTM_BLOCKS);
    }
}

// ======= M=32 partial fp32 GEMM tile =======
#define PART_TILE(LOAD_A, LOAD_B, KSLICE, NTOT)                                     \
    {                                                                               \
        float acc[4][4];                                                            \
        _Pragma("unroll") for (int r = 0; r < 4; r++)                               \
        _Pragma("unroll") for (int g = 0; g < 4; g++) acc[r][g] = 0.f;              \
        for (int kt = 0; kt < (KSLICE); kt += 16) {                                 \
            _Pragma("unroll") for (int l = 0; l < 2; l++) {                         \
                int idx = tid + l * 256;                                            \
                int kk = idx >> 5; int nn = (idx & 31) * 4;                         \
                float4 v = make_float4(0.f, 0.f, 0.f, 0.f);                         \
                int kl = kt + kk;                                                   \
                if (kl < (KSLICE) && (n0 + nn) < (NTOT)) { int kg = k0 + kl; LOAD_B; } \
                *(float4*)&Bs[kk][nn] = v;                                          \
            }                                                                       \
            _Pragma("unroll") for (int l = 0; l < 2; l++) {                         \
                int idx = tid + l * 256;                                            \
                int r = idx >> 4; int kk = idx & 15;                                \
                float v = 0.f;                                                      \
                int kl = kt + kk;                                                   \
                if (kl < (KSLICE)) { int kg = k0 + kl; LOAD_A; }                    \
                As[r][kk] = v;                                                      \
            }                                                                       \
            __syncthreads();                                                        \
            _Pragma("unroll") for (int kq = 0; kq < 4; kq++) {                      \
                float4 a4[4];                                                       \
                _Pragma("unroll") for (int r = 0; r < 4; r++)                       \
                    a4[r] = *(const float4*)&As[ty * 4 + r][kq * 4];                \
                _Pragma("unroll") for (int kk = 0; kk < 4; kk++) {                  \
                    float4 b4 = *(const float4*)&Bs[kq * 4 + kk][tx * 4];           \
                    _Pragma("unroll") for (int r = 0; r < 4; r++) {                 \
                        float a = (kk == 0) ? a4[r].x : (kk == 1) ? a4[r].y         \
                                  : (kk == 2) ? a4[r].z : a4[r].w;                  \
                        acc[r][0] += a * b4.x; acc[r][1] += a * b4.y;               \
                        acc[r][2] += a * b4.z; acc[r][3] += a * b4.w;               \
                    }                                                               \
                }                                                                   \
            }                                                                       \
            __syncthreads();                                                        \
        }                                                                           \
        int nn = n0 + tx * 4;                                                       \
        if (nn < (NTOT)) {                                                          \
            _Pragma("unroll") for (int r = 0; r < 4; r++)                           \
                *(float4*)(outp + (long)(ty * 4 + r) * (NTOT) + nn) =               \
                    make_float4(acc[r][0], acc[r][1], acc[r][2], acc[r][3]);        \
        }                                                                           \
    }

// ---------------- decoder step kernels (per-step launches) ----------------
__global__ void dec_part(const float* __restrict__ hdin)
{
    __shared__ float Bs[16][128];
    __shared__ float As[32][16];
    const int tid = threadIdx.x;
    const int tx = tid & 31, ty = tid >> 5;
    const int jt = blockIdx.x, ks = blockIdx.y;
    const int n0 = jt * 128;
    const int k0 = ks * 200;
    float* outp = g_dpart + (long)ks * BB * 4 * HH;
    PART_TILE(v = (kg < HH) ? g_oprev[r * HH + kg] : hdin[r * HH + kg - HH],
              v = (kg < HH) ? *(const float4*)(g_wxo_t + (long)kg * 4 * HH + n0 + nn)
                            : *(const float4*)(g_whd_t + (long)(kg - HH) * 4 * HH + n0 + nn),
              200, 4 * HH)
}

__global__ void dec_combine(float* __restrict__ hdout, int t)
{
    int idx = blockIdx.x * 256 + threadIdx.x;
    if (idx >= BB * HH) return;
    const int b = idx / HH, j = idx % HH;
    const float4* P = (const float4*)g_dpart;
    float4 g4 = P[(long)b * HH + j];
#pragma unroll
    for (int kq = 1; kq < DKS; kq++) {
        float4 p = P[((long)kq * BB + b) * HH + j];
        g4.x += p.x; g4.y += p.y; g4.z += p.z; g4.w += p.w;
    }
    const long xb = ((long)b * QL + t) * 4 * HH;
    float gi = g4.x + g_qx[xb + j];
    float gf = g4.y + g_qx[xb + HH + j];
    float gg = g4.z + g_qx[xb + 2 * HH + j];
    float go = g4.w + g_qx[xb + 3 * HH + j];
    float c = g_cd[b * HH + j];
    c = sigf(gf) * c + sigf(gi) * tanhf(gg);
    g_cd[b * HH + j] = c;
    hdout[b * HH + j] = sigf(go) * tanhf(c);
}

// scores + masked softmax -> g_alpha[b][c]  (512 threads, float4 dot)
__global__ void attn_score(const float* __restrict__ hd, const int* __restrict__ cw)
{
    const int b = blockIdx.x;
    const int tid = threadIdx.x;
    __shared__ float sh_h[HH];
    __shared__ float sh_e[CL];
    __shared__ float sred[16];
    const int warp = tid >> 5, lane = tid & 31;

    for (int i = tid; i < HH; i += 512) sh_h[i] = hd[b * HH + i];
    __syncthreads();
    const float4* h4 = (const float4*)sh_h;
    for (int c = warp; c < CL; c += 16) {
        const float4* ep4 = (const float4*)(g_encp + ((long)b * CL + c) * HH);
        float s = 0.f;
        for (int k = lane; k < HH / 4; k += 32) {
            float4 e = ep4[k], hh = h4[k];
            s += e.x * hh.x + e.y * hh.y + e.z * hh.z + e.w * hh.w;
        }
        for (int o = 16; o; o >>= 1) s += __shfl_down_sync(0xffffffffu, s, o);
        if (!lane) sh_e[c] = (cw[b * CL + c] != 0) ? s : -1e30f;
    }
    __syncthreads();

    float m = -1e30f;
    for (int c = tid; c < CL; c += 512) m = fmaxf(m, sh_e[c]);
    for (int o = 16; o; o >>= 1) m = fmaxf(m, __shfl_xor_sync(0xffffffffu, m, o));
    if (!lane) sred[warp] = m;
    __syncthreads();
    if (tid == 0) {
        float v = sred[0];
        for (int w = 1; w < 16; w++) v = fmaxf(v, sred[w]);
        sred[0] = v;
    }
    __syncthreads();
    m = sred[0];
    __syncthreads();

    float s = 0.f;
    for (int c = tid; c < CL; c += 512) {
        float e = expf(sh_e[c] - m);
        sh_e[c] = e;
        s += e;
    }
    for (int o = 16; o; o >>= 1) s += __shfl_xor_sync(0xffffffffu, s, o);
    if (!lane) sred[warp] = s;
    __syncthreads();
    if (tid == 0) {
        float v = 0.f;
        for (int w = 0; w < 16; w++) v += sred[w];
        sred[0] = v;
    }
    __syncthreads();
    const float inv = 1.0f / sred[0];
    for (int c = tid; c < CL; c += 512)
        g_alpha[b * CL + c] = sh_e[c] * inv;
}

__global__ void attn_ctx()
{
    const int b = blockIdx.y;
    const int d = blockIdx.x * 256 + threadIdx.x;
    __shared__ float sal[CL];
    for (int c = threadIdx.x; c < CL; c += 256) sal[c] = g_alpha[b * CL + c];
    __syncthreads();
    if (d >= 2 * HH) return;
    const float* eb = g_enc + (long)b * CL * 2 * HH + d;
    float acc = 0.f;
#pragma unroll 8
    for (int c = 0; c < CL; c++) acc += sal[c] * eb[(long)c * 2 * HH];
    g_a[b * 2 * HH + d] = acc;
}

__global__ void comb_part(const float* __restrict__ hdnew, const float* __restrict__ Wcomb)
{
    __shared__ float Bs[16][128];
    __shared__ float As[32][16];
    const int tid = threadIdx.x;
    const int tx = tid & 31, ty = tid >> 5;
    const int jt = blockIdx.x, ks = blockIdx.y;
    const int n0 = jt * 128;
    const int k0 = ks * 75;
    float* outp = g_cpart + (long)ks * BB * HH;
    PART_TILE(v = (kg < HH) ? hdnew[r * HH + kg] : g_a[r * 2 * HH + kg - HH],
              v = *(const float4*)(Wcomb + (long)kg * HH + n0 + nn),
              75, HH)
}

__global__ void comb_combine(int t)
{
    int idx = blockIdx.x * 256 + threadIdx.x;
    if (idx >= BB * HH) return;
    const int b = idx / HH, j = idx % HH;
    float s = 0.f;
#pragma unroll
    for (int kq = 0; kq < CKS; kq++) s += g_cpart[((long)kq * BB + b) * HH + j];
    float O = tanhf(s);
    g_oprev[b * HH + j] = O;
    g_outs[((long)b * QL + t) * HH + j] = O;
}

// ---------------- h0/c0 projection + o_prev init ----------------
__global__ void h0c0_kernel(const float* __restrict__ Whi, const float* __restrict__ Wci)
{
    int idx = blockIdx.x * 256 + threadIdx.x;
    if (idx >= BB * HH) return;
    int b = idx / HH, j = idx % HH;
    const float* hf = g_stateH + 0 * BB * HH;
    const float* hb = g_stateH + 2 * BB * HH;
    const float* cf = g_stateC;
    const float* cb = g_stateC + BB * HH;
    float ah = 0.f, ac = 0.f;
    for (int k = 0; k < HH; k++) {
        ah += hf[b * HH + k] * Whi[k * HH + j];
        ac += cf[b * HH + k] * Wci[k * HH + j];
    }
    for (int k = 0; k < HH; k++) {
        ah += hb[b * HH + k] * Whi[(HH + k) * HH + j];
        ac += cb[b * HH + k] * Wci[(HH + k) * HH + j];
    }
    g_hd[0][idx] = ah;
    g_cd[idx] = ac;
    g_oprev[idx] = 0.f;
}

// ---------------- log-softmax over vocab, in place (512 thr, float4) --------
__global__ void logsoftmax_kernel(float* __restrict__ x)
{
    const long base = (long)blockIdx.x * VOC;
    const int tid = threadIdx.x;
    __shared__ float sred[16];
    const int warp = tid >> 5, lane = tid & 31;
    float4* x4 = (float4*)(x + base);
    const int N4 = VOC / 4;   // 12500

    float m = -1e30f;
    for (int i = tid; i < N4; i += 512) {
        float4 v = x4[i];
        m = fmaxf(m, fmaxf(fmaxf(v.x, v.y), fmaxf(v.z, v.w)));
    }
    for (int o = 16; o; o >>= 1) m = fmaxf(m, __shfl_xor_sync(0xffffffffu, m, o));
    if (!lane) sred[warp] = m;
    __syncthreads();
    if (tid == 0) {
        float v = sred[0];
        for (int w = 1; w < 16; w++) v = fmaxf(v, sred[w]);
        sred[0] = v;
    }
    __syncthreads();
    m = sred[0];
    __syncthreads();

    float s = 0.f;
    for (int i = tid; i < N4; i += 512) {
        float4 v = x4[i];
        s += expf(v.x - m) + expf(v.y - m) + expf(v.z - m) + expf(v.w - m);
    }
    for (int o = 16; o; o >>= 1) s += __shfl_xor_sync(0xffffffffu, s, o);
    if (!lane) sred[warp] = s;
    __syncthreads();
    if (tid == 0) {
        float v = 0.f;
        for (int w = 0; w < 16; w++) v += sred[w];
        sred[0] = v;
    }
    __syncthreads();
    const float lse = m + logf(sred[0]);

    for (int i = tid; i < N4; i += 512) {
        float4 v = x4[i];
        v.x -= lse; v.y -= lse; v.z -= lse; v.w -= lse;
        x4[i] = v;
    }
}

// ---------------- launch ----------------
extern "C" void kernel_launch(void* const* d_in, const int* in_sizes, int n_in,
                              void* d_out, int out_size)
{
    (void)in_sizes; (void)n_in; (void)out_size;
    const int*   cw      = (const int*)  d_in[0];
    const int*   qw      = (const int*)  d_in[1];
    const float* W_emb   = (const float*)d_in[2];
    const float* emb_prj = (const float*)d_in[3];
    const float* Wx_f    = (const float*)d_in[4];
    const float* Wh_f    = (const float*)d_in[5];
    const float* b_f     = (const float*)d_in[6];
    const float* Wx_b    = (const float*)d_in[7];
    const float* Wh_b    = (const float*)d_in[8];
    const float* b_b     = (const float*)d_in[9];
    const float* Wh_init = (const float*)d_in[10];
    const float* Wc_init = (const float*)d_in[11];
    const float* Wx_d    = (const float*)d_in[12];
    const float* Wh_d    = (const float*)d_in[13];
    const float* b_d     = (const float*)d_in[14];
    const float* W_att   = (const float*)d_in[15];
    const float* W_comb  = (const float*)d_in[16];
    const float* W_gen   = (const float*)d_in[17];
    const float* b_gen   = (const float*)d_in[18];
    float* out = (float*)d_out;

    void *p_cemb, *p_qemb, *p_xwf, *p_xwb, *p_qx;
    void *p_whd, *p_wxo, *p_whfnk, *p_whbnk;
    void *p_embt, *p_wxft, *p_wxbt, *p_wxdqt, *p_watt, *p_wgent;
    void *p_enc, *p_encp, *p_outs, *p_SH, *p_SC, *p_lpart;
    void *p_lcnt, *p_lgen, *p_hd;
    cudaGetSymbolAddress(&p_cemb,  g_cemb);
    cudaGetSymbolAddress(&p_qemb,  g_qemb);
    cudaGetSymbolAddress(&p_xwf,   g_xwf);
    cudaGetSymbolAddress(&p_xwb,   g_xwb);
    cudaGetSymbolAddress(&p_qx,    g_qx);
    cudaGetSymbolAddress(&p_whd,   g_whd_t);
    cudaGetSymbolAddress(&p_wxo,   g_wxo_t);
    cudaGetSymbolAddress(&p_whfnk, g_whf_nk);
    cudaGetSymbolAddress(&p_whbnk, g_whb_nk);
    cudaGetSymbolAddress(&p_embt,  g_embt);
    cudaGetSymbolAddress(&p_wxft,  g_wxft);
    cudaGetSymbolAddress(&p_wxbt,  g_wxbt);
    cudaGetSymbolAddress(&p_wxdqt, g_wxdqt);
    cudaGetSymbolAddress(&p_watt,  g_watt);
    cudaGetSymbolAddress(&p_wgent, g_wgent);
    cudaGetSymbolAddress(&p_enc,   g_enc);
    cudaGetSymbolAddress(&p_encp,  g_encp);
    cudaGetSymbolAddress(&p_outs,  g_outs);
    cudaGetSymbolAddress(&p_SH,    g_stateH);
    cudaGetSymbolAddress(&p_SC,    g_stateC);
    cudaGetSymbolAddress(&p_lpart, g_lpart2);
    cudaGetSymbolAddress(&p_lcnt,  g_lbar_cnt);
    cudaGetSymbolAddress(&p_lgen,  g_lbar_genw);
    cudaGetSymbolAddress(&p_hd,    g_hd);
    float* hd0 = (float*)p_hd;
    float* hd1 = hd0 + BB * HH;

    cudaFuncSetAttribute(lstm_persist, cudaFuncAttributeMaxDynamicSharedMemorySize,
                         LSTM_SMEM_BYTES);

    zero_state_kernel<<<300, 256>>>();
    transpose_t<<<dim3(19, 10), dim3(32, 8)>>>(emb_prj, (float*)p_embt, EMB, HH, HH);
    transpose_t<<<dim3(75, 19), dim3(32, 8)>>>(Wx_f, (float*)p_wxft, HH, 4 * HH, 4 * HH);
    gemm_tf32<<<dim3(5, 200), 256>>>(W_emb, cw, (float*)p_embt, nullptr,
                                     (float*)p_cemb, BB * CL, HH, EMB);            // ncu window
    gemm_tf32<<<dim3(19, 200), 256>>>((float*)p_cemb, nullptr, (float*)p_wxft, b_f,
                                      (float*)p_xwf, BB * CL, 4 * HH, HH);
    transpose_t<<<dim3(75, 19), dim3(32, 8)>>>(Wx_b, (float*)p_wxbt, HH, 4 * HH, 4 * HH);
    gemm_tf32<<<dim3(19, 200), 256>>>((float*)p_cemb, nullptr, (float*)p_wxbt, b_b,
                                      (float*)p_xwb, BB * CL, 4 * HH, HH);
    gemm_tf32<<<dim3(5, 15), 256>>>(W_emb, qw, (float*)p_embt, nullptr,
                                    (float*)p_qemb, BB * QL, HH, EMB);
    transpose_t<<<dim3(75, 19), dim3(32, 8)>>>(Wx_d, (float*)p_wxdqt, HH, 4 * HH, 4 * HH);
    gemm_tf32<<<dim3(19, 15), 256>>>((float*)p_qemb, nullptr, (float*)p_wxdqt, b_d,
                                     (float*)p_qx, BB * QL, 4 * HH, HH);
    transpose_gates_nk<<<5625, 256>>>(Wh_f, (float*)p_whfnk);
    transpose_gates_nk<<<5625, 256>>>(Wh_b, (float*)p_whbnk);
    transpose_gates<<<1407, 256>>>(Wh_d, (float*)p_whd);
    transpose_gates<<<1407, 256>>>(Wx_d + HH * 4 * HH, (float*)p_wxo);

    // persistent BiLSTM (512 threads; ~3.5 ms measured)
    lstm_persist<<<LSTM_BLOCKS, LTHREADS, LSTM_SMEM_BYTES>>>(
        (const float*)p_whfnk, (const float*)p_whbnk,
        (const float*)p_xwf, (const float*)p_xwb,
        (float*)p_SH, (float*)p_SC, (float*)p_enc, (float*)p_lpart,
        (unsigned*)p_lcnt, (unsigned*)p_lgen);

    h0c0_kernel<<<75, 256>>>(Wh_init, Wc_init);
    transpose_t<<<dim3(19, 38), dim3(32, 8)>>>(W_att, (float*)p_watt, 2 * HH, HH, HH);
    gemm_tf32<<<dim3(5, 200), 256>>>((float*)p_enc, nullptr, (float*)p_watt, nullptr,
                                     (float*)p_encp, BB * CL, HH, 2 * HH);

    // decoder: per-step launches (graph edges do the sync)
    for (int t = 0; t < QL; t++) {
        const float* hin = (t & 1) ? hd1 : hd0;
        float* hout      = (t & 1) ? hd0 : hd1;
        dec_part<<<dim3(19, DKS), 256>>>(hin);
        dec_combine<<<75, 256>>>(hout, t);
        attn_score<<<BB, 512>>>(hout, cw);
        attn_ctx<<<dim3(5, BB), 256>>>();
        comb_part<<<dim3(5, CKS), 256>>>(hout, W_comb);
        comb_combine<<<75, 256>>>(t);
    }

    transpose_t<<<dim3(1563, 19), dim3(32, 8)>>>(W_gen, (float*)p_wgent, HH, VOC, VOC);
    gemm_tf32<<<dim3(391, 15), 256>>>((float*)p_outs, nullptr, (float*)p_wgent, b_gen,
                                      out, BB * QL, VOC, HH);
    logsoftmax_kernel<<<BB * QL, 512>>>(out);
}

// round 15
// speedup vs baseline: 1.0575x; 1.0575x over previous
#include <cuda_runtime.h>
#include <math.h>

#define BB 32
#define CL 400
#define QL 30
#define HH 600
#define VOC 50000
#define EMB 300

#define LKS 6    // lstm k-split (kslice 100, padded to 112)
#define DKS 6    // decoder k-split (K=1200, kslice 200)
#define CKS 24   // comb k-split (K=1800, kslice 75)

#define LSTM_BLOCKS 120   // 10 n-tiles x LKS x 2 dirs
#define LTHREADS 512      // 16 warps

#define WS_STRIDE 116
#define WS_FLOATS (256 * WS_STRIDE)   // 29696
#define XC_FLOATS (32 * 260)          // 8320
#define LSTM_SMEM_BYTES ((WS_FLOATS + XC_FLOATS) * 4)   // 152064

// ---------------- scratch (device globals; allocation-free) ----------------
__device__ float g_cemb[BB*CL*HH];
__device__ float g_qemb[BB*QL*HH];
__device__ float g_xwf [BB*CL*4*HH];        // plain gate-blocked x-parts [row][g*600+j]
__device__ float g_xwb [BB*CL*4*HH];
__device__ float g_qx  [BB*QL*4*HH];
__device__ float g_whd_t[HH*HH*4];          // [k][j*4+g]
__device__ float g_wxo_t[HH*HH*4];
__device__ float g_whf_nk[4*HH*HH];         // [n=j*4+g][k]
__device__ float g_whb_nk[4*HH*HH];
__device__ float g_embt [HH*EMB];
__device__ float g_wxft [4*HH*HH];
__device__ float g_wxbt [4*HH*HH];
__device__ float g_wxdqt[4*HH*HH];
__device__ float g_watt [HH*2*HH];
__device__ float g_enc [BB*CL*2*HH];
__device__ float g_encp[BB*CL*HH];
__device__ float g_stateH[2*2*BB*HH];       // [dir][phase][b][j]
__device__ float g_stateC[2*BB*HH];
__device__ float g_hd[2][BB*HH];
__device__ float g_cd[BB*HH];
__device__ float g_oprev[BB*HH];
__device__ float g_alpha[BB*CL];
__device__ float g_a[BB*2*HH];
__device__ float g_outs[BB*QL*HH];
__device__ float g_lpart2[2*LKS*BB*4*HH];
__device__ float g_dpart[DKS*BB*4*HH];
__device__ float g_cpart[CKS*BB*HH];

// LSTM barrier: cnt and gen on separate 128B lines
__device__ __align__(128) unsigned g_lbar_cnt[32];
__device__ __align__(128) unsigned g_lbar_genw[32];

__device__ __forceinline__ void grid_sync_ptr(unsigned* cnt, volatile unsigned* gen, unsigned nb)
{
    __syncthreads();
    if (threadIdx.x == 0) {
        unsigned g = *gen;
        __threadfence();
        if (atomicAdd(cnt, 1u) == nb - 1u) {
            *cnt = 0u;
            __threadfence();
            *gen = g + 1u;
        } else {
            while (*gen == g) { }
            __threadfence();
        }
    }
    __syncthreads();
}

__device__ __forceinline__ float sigf(float x) { return 1.0f / (1.0f + expf(-x)); }

__device__ __forceinline__ float tf32r(float f)
{
    unsigned u; asm("cvt.rna.tf32.f32 %0, %1;" : "=r"(u) : "f"(f));
    return __uint_as_float(u);
}
__device__ __forceinline__ float4 tf32r4(float4 v)
{
    return make_float4(tf32r(v.x), tf32r(v.y), tf32r(v.z), tf32r(v.w));
}
__device__ __forceinline__ void mma8(float* d, const unsigned* a, const unsigned* b)
{
    asm volatile("mma.sync.aligned.m16n8k8.row.col.f32.tf32.tf32.f32 "
        "{%0,%1,%2,%3}, {%4,%5,%6,%7}, {%8,%9}, {%0,%1,%2,%3};"
        : "+f"(d[0]), "+f"(d[1]), "+f"(d[2]), "+f"(d[3])
        : "r"(a[0]), "r"(a[1]), "r"(a[2]), "r"(a[3]), "r"(b[0]), "r"(b[1]));
}

__device__ __forceinline__ unsigned smem_u32p(const void* p)
{
    return (unsigned)__cvta_generic_to_shared(p);
}
__device__ __forceinline__ void cpa16(unsigned dst, const void* src, int bytes)
{
    asm volatile("cp.async.cg.shared.global [%0], [%1], 16, %2;"
                 :: "r"(dst), "l"(src), "r"(bytes) : "memory");
}

// ---------------- tf32 GEMM v2: 128N x 64M, cp.async 2-stage (best measured) -
// C[M][N] = gather(X)[M][K] @ W, W given as Wt[N][K] (k-contiguous rows)
__global__ void gemm_tf32(const float* __restrict__ X, const int* __restrict__ gidx,
                          const float* __restrict__ Wt, const float* __restrict__ bias,
                          float* __restrict__ C, int M, int N, int K)
{
    __shared__ float smem[8448];    // WsB[2]:2x2560, XsB[2]:2x1280 (=7680); Cs overlay 8448
    float* WsB[2] = { smem, smem + 2560 };
    float* XsB[2] = { smem + 5120, smem + 6400 };
    const int tid = threadIdx.x;
    const int warp = tid >> 5, lane = tid & 31;
    const int lq = lane >> 2, lr = lane & 3;
    const int wn = (warp & 3) * 32, wm = (warp >> 2) * 32;
    const int bn0 = blockIdx.x * 128;
    const int bm0 = blockIdx.y * 64;

    const int kqw = (tid & 3) * 4;
    const int n_0 = tid >> 2;
    const int n_1 = (tid + 256) >> 2;
    const int m_x = tid >> 2;
    const float* rowW0 = (bn0 + n_0 < N) ? Wt + (long)(bn0 + n_0) * K : nullptr;
    const float* rowW1 = (bn0 + n_1 < N) ? Wt + (long)(bn0 + n_1) * K : nullptr;
    const float* rowX  = nullptr;
    if (bm0 + m_x < M)
        rowX = X + (gidx ? (long)gidx[bm0 + m_x] * K : (long)(bm0 + m_x) * K);

    unsigned wsa0[2], wsa1[2], xsa[2];
#pragma unroll
    for (int b = 0; b < 2; b++) {
        wsa0[b] = smem_u32p(&WsB[b][n_0 * 20 + kqw]);
        wsa1[b] = smem_u32p(&WsB[b][n_1 * 20 + kqw]);
        xsa[b]  = smem_u32p(&XsB[b][m_x * 20 + kqw]);
    }

    const int KT = (K + 15) / 16;

#define G_ISSUE(KT0, BUF) do {                                              \
        int kk_ = (KT0) * 16 + kqw;                                         \
        int in_ = (kk_ < K);                                                \
        int b0_ = (rowW0 && in_) ? 16 : 0;                                  \
        int b1_ = (rowW1 && in_) ? 16 : 0;                                  \
        int bx_ = (rowX  && in_) ? 16 : 0;                                  \
        cpa16(wsa0[BUF], b0_ ? rowW0 + kk_ : Wt, b0_);                      \
        cpa16(wsa1[BUF], b1_ ? rowW1 + kk_ : Wt, b1_);                      \
        cpa16(xsa[BUF],  bx_ ? rowX  + kk_ : Wt, bx_);                      \
        asm volatile("cp.async.commit_group;" ::: "memory");                \
    } while (0)

    float acc[2][4][4];
#pragma unroll
    for (int t = 0; t < 2; t++)
#pragma unroll
        for (int u = 0; u < 4; u++)
#pragma unroll
            for (int e = 0; e < 4; e++) acc[t][u][e] = 0.f;

    G_ISSUE(0, 0);
    for (int kt = 0; kt < KT; kt++) {
        if (kt + 1 < KT) {
            G_ISSUE(kt + 1, (kt + 1) & 1);
            asm volatile("cp.async.wait_group 1;" ::: "memory");
        } else {
            asm volatile("cp.async.wait_group 0;" ::: "memory");
        }
        __syncthreads();

        const float* Ws = WsB[kt & 1];
        const float* Xs = XsB[kt & 1];
#pragma unroll
        for (int kc = 0; kc < 2; kc++) {
            const int kb = kc * 8 + lr;
            unsigned a[2][4], b[4][2];
#pragma unroll
            for (int t = 0; t < 2; t++) {
                const float* p = Ws + (wn + t * 16 + lq) * 20 + kb;
                a[t][0] = __float_as_uint(p[0]);
                a[t][1] = __float_as_uint(p[8 * 20]);
                a[t][2] = __float_as_uint(p[4]);
                a[t][3] = __float_as_uint(p[8 * 20 + 4]);
            }
#pragma unroll
            for (int u = 0; u < 4; u++) {
                const float* p = Xs + (wm + u * 8 + lq) * 20 + kb;
                b[u][0] = __float_as_uint(p[0]);
                b[u][1] = __float_as_uint(p[4]);
            }
#pragma unroll
            for (int t = 0; t < 2; t++)
#pragma unroll
                for (int u = 0; u < 4; u++)
                    mma8(acc[t][u], a[t], b[u]);
        }
        __syncthreads();
    }
#undef G_ISSUE

    float* Cs = smem;
#pragma unroll
    for (int t = 0; t < 2; t++)
#pragma unroll
        for (int u = 0; u < 4; u++) {
            int nl = wn + t * 16 + lq;
            int m = wm + u * 8 + lr * 2;
            Cs[m * 132 + nl]           = acc[t][u][0];
            Cs[(m + 1) * 132 + nl]     = acc[t][u][1];
            Cs[m * 132 + nl + 8]       = acc[t][u][2];
            Cs[(m + 1) * 132 + nl + 8] = acc[t][u][3];
        }
    __syncthreads();
#pragma unroll
    for (int l = 0; l < 8; l++) {
        int idx = tid + l * 256;
        int m = idx >> 5, nl4 = (idx & 31) * 4;
        int gm = bm0 + m, gn = bn0 + nl4;
        if (gm < M && gn < N) {
            float4 v = *(float4*)&Cs[m * 132 + nl4];
            if (gn + 3 < N) {
                if (bias) {
                    v.x += bias[gn]; v.y += bias[gn + 1];
                    v.z += bias[gn + 2]; v.w += bias[gn + 3];
                }
                *(float4*)(C + (long)gm * N + gn) = v;
            } else {
                float vv[4] = {v.x, v.y, v.z, v.w};
                for (int e = 0; e < 4; e++)
                    if (gn + e < N)
                        C[(long)gm * N + gn + e] = vv[e] + (bias ? bias[gn + e] : 0.f);
            }
        }
    }
}

// ---------------- tf32 GEMM (B natural layout): C[M][N] = X[M][K] @ W[K][N] --
// W rows are n-contiguous: no pre-transpose needed. Smem W tile [16][136]
// (stride 136 -> a-fragment lanes hit banks lr*8+lq, conflict-free).
// Requires N % 4 == 0 and bn0 % 4 == 0 (true here: N = 50000).
__global__ void gemm_tf32_bn(const float* __restrict__ X,
                             const float* __restrict__ W, const float* __restrict__ bias,
                             float* __restrict__ C, int M, int N, int K)
{
    __shared__ float smem[8448];    // Wk[2]:2x2176 (=4352), Xs[2]:2x1280 (6912); Cs overlay
    float* WkB[2] = { smem, smem + 2176 };
    float* XsB[2] = { smem + 4352, smem + 5632 };
    const int tid = threadIdx.x;
    const int warp = tid >> 5, lane = tid & 31;
    const int lq = lane >> 2, lr = lane & 3;
    const int wn = (warp & 3) * 32, wm = (warp >> 2) * 32;
    const int bn0 = blockIdx.x * 128;
    const int bm0 = blockIdx.y * 64;

    // W copy descriptors: 512 float4 per stage, 2 per thread
    const int wk0 = tid >> 5;               // k row 0..7  (first half)
    const int wk1 = 8 + (tid >> 5);         // k row 8..15 (second half)
    const int wn4 = (tid & 31) * 4;         // n offset within tile
    const int gw_n = bn0 + wn4;
    const int wn_ok = (gw_n + 3 < N) || (gw_n < N && (N & 3) == 0);
    // (N % 4 == 0 guaranteed; a float4 is either fully in range or fully out)
    const int wvalid = (gw_n < N);

    // X copy descriptors (same as gemm_tf32)
    const int kqx = (tid & 3) * 4;
    const int m_x = tid >> 2;
    const float* rowX = (bm0 + m_x < M) ? X + (long)(bm0 + m_x) * K : nullptr;

    unsigned wka0[2], wka1[2], xsa[2];
#pragma unroll
    for (int b = 0; b < 2; b++) {
        wka0[b] = smem_u32p(&WkB[b][wk0 * 136 + wn4]);
        wka1[b] = smem_u32p(&WkB[b][wk1 * 136 + wn4]);
        xsa[b]  = smem_u32p(&XsB[b][m_x * 20 + kqx]);
    }
    (void)wn_ok;

    const int KT = (K + 15) / 16;

#define GB_ISSUE(KT0, BUF) do {                                             \
        int kx_ = (KT0) * 16 + kqx;                                         \
        int bx_ = (rowX && kx_ < K) ? 16 : 0;                               \
        int kr0_ = (KT0) * 16 + wk0;                                        \
        int kr1_ = (KT0) * 16 + wk1;                                        \
        int b0_ = (wvalid && kr0_ < K) ? 16 : 0;                            \
        int b1_ = (wvalid && kr1_ < K) ? 16 : 0;                            \
        cpa16(wka0[BUF], b0_ ? W + (long)kr0_ * N + gw_n : W, b0_);         \
        cpa16(wka1[BUF], b1_ ? W + (long)kr1_ * N + gw_n : W, b1_);         \
        cpa16(xsa[BUF],  bx_ ? rowX + kx_ : W, bx_);                        \
        asm volatile("cp.async.commit_group;" ::: "memory");                \
    } while (0)

    float acc[2][4][4];
#pragma unroll
    for (int t = 0; t < 2; t++)
#pragma unroll
        for (int u = 0; u < 4; u++)
#pragma unroll
            for (int e = 0; e < 4; e++) acc[t][u][e] = 0.f;

    GB_ISSUE(0, 0);
    for (int kt = 0; kt < KT; kt++) {
        if (kt + 1 < KT) {
            GB_ISSUE(kt + 1, (kt + 1) & 1);
            asm volatile("cp.async.wait_group 1;" ::: "memory");
        } else {
            asm volatile("cp.async.wait_group 0;" ::: "memory");
        }
        __syncthreads();

        const float* Wk = WkB[kt & 1];
        const float* Xs = XsB[kt & 1];
#pragma unroll
        for (int kc = 0; kc < 2; kc++) {
            const int kb = kc * 8 + lr;
            unsigned a[2][4], b[4][2];
#pragma unroll
            for (int t = 0; t < 2; t++) {
                const float* p = Wk + kb * 136 + wn + t * 16 + lq;
                a[t][0] = __float_as_uint(p[0]);
                a[t][1] = __float_as_uint(p[8]);
                a[t][2] = __float_as_uint(p[4 * 136]);
                a[t][3] = __float_as_uint(p[4 * 136 + 8]);
            }
#pragma unroll
            for (int u = 0; u < 4; u++) {
                const float* p = Xs + (wm + u * 8 + lq) * 20 + kb;
                b[u][0] = __float_as_uint(p[0]);
                b[u][1] = __float_as_uint(p[4]);
            }
#pragma unroll
            for (int t = 0; t < 2; t++)
#pragma unroll
                for (int u = 0; u < 4; u++)
                    mma8(acc[t][u], a[t], b[u]);
        }
        __syncthreads();
    }
#undef GB_ISSUE

    float* Cs = smem;
#pragma unroll
    for (int t = 0; t < 2; t++)
#pragma unroll
        for (int u = 0; u < 4; u++) {
            int nl = wn + t * 16 + lq;
            int m = wm + u * 8 + lr * 2;
            Cs[m * 132 + nl]           = acc[t][u][0];
            Cs[(m + 1) * 132 + nl]     = acc[t][u][1];
            Cs[m * 132 + nl + 8]       = acc[t][u][2];
            Cs[(m + 1) * 132 + nl + 8] = acc[t][u][3];
        }
    __syncthreads();
#pragma unroll
    for (int l = 0; l < 8; l++) {
        int idx = tid + l * 256;
        int m = idx >> 5, nl4 = (idx & 31) * 4;
        int gm = bm0 + m, gn = bn0 + nl4;
        if (gm < M && gn < N) {
            float4 v = *(float4*)&Cs[m * 132 + nl4];
            if (bias) {
                v.x += bias[gn]; v.y += bias[gn + 1];
                v.z += bias[gn + 2]; v.w += bias[gn + 3];
            }
            *(float4*)(C + (long)gm * N + gn) = v;
        }
    }
}

// ---------------- small helpers ----------------
__global__ void zero_state_kernel()
{
    int i = blockIdx.x * 256 + threadIdx.x;
    if (i < 2 * 2 * BB * HH) g_stateH[i] = 0.f;
    if (i < 2 * BB * HH)     g_stateC[i] = 0.f;
    if (i < 32) { g_lbar_cnt[i] = 0u; g_lbar_genw[i] = 0u; }
}

__global__ void transpose_gates(const float* __restrict__ W, float* __restrict__ Wt)
{
    int idx = blockIdx.x * 256 + threadIdx.x;
    if (idx >= HH * HH) return;
    int k = idx / HH, j = idx % HH;
    float4 v;
    v.x = W[k * 4 * HH + j];
    v.y = W[k * 4 * HH + HH + j];
    v.z = W[k * 4 * HH + 2 * HH + j];
    v.w = W[k * 4 * HH + 3 * HH + j];
    ((float4*)Wt)[idx] = v;
}

__global__ void transpose_gates_nk(const float* __restrict__ W, float* __restrict__ out)
{
    long idx = (long)blockIdx.x * 256 + threadIdx.x;
    if (idx >= (long)4 * HH * HH) return;
    int n = (int)(idx / HH), k = (int)(idx % HH);
    out[idx] = W[(long)k * 4 * HH + (n & 3) * HH + (n >> 2)];
}

__global__ void transpose_t(const float* __restrict__ in, float* __restrict__ out,
                            int K, int N, int ldin)
{
    __shared__ float t[32][33];
    int kb = blockIdx.y * 32, nb = blockIdx.x * 32;
    int x = threadIdx.x, y = threadIdx.y;
    for (int i = y; i < 32; i += 8)
        t[i][x] = (kb + i < K && nb + x < N) ? in[(long)(kb + i) * ldin + nb + x] : 0.f;
    __syncthreads();
    for (int i = y; i < 32; i += 8)
        if (nb + i < N && kb + x < K)
            out[(long)(nb + i) * K + kb + x] = t[x][i];
}

// ---------------- persistent BiLSTM: 512 threads, weights smem-resident -----
__global__ void lstm_persist(const float* __restrict__ Wf, const float* __restrict__ Wb,
                             const float* __restrict__ xf, const float* __restrict__ xb,
                             float* __restrict__ SH, float* __restrict__ SC,
                             float* __restrict__ enc, float* __restrict__ lpart,
                             unsigned* bcnt, unsigned* bgenw)
{
    extern __shared__ float dsm[];
    float* Ws = dsm;
    float* Xs = dsm + WS_FLOATS;
    float* Cs = dsm + WS_FLOATS;

    const int bx = blockIdx.x;
    const int tid = threadIdx.x;
    const int warp = tid >> 5, lane = tid & 31;
    const int lq = lane >> 2, lr = lane & 3;
    const int nb = bx % 10;
    const int ks = (bx / 10) % LKS;
    const int dir = bx / (10 * LKS);
    const int n0 = nb * 256;
    const int k0 = ks * 100;
    const int wn = warp * 16;
    const float* Wnk = dir ? Wb : Wf;
    float* outP = lpart + (long)(dir * LKS + ks) * BB * 4 * HH;
    volatile unsigned* bgen = (volatile unsigned*)bgenw;

    for (int idx4 = tid; idx4 < 256 * 29; idx4 += LTHREADS) {
        int n = idx4 / 29, kq = (idx4 % 29) * 4;
        float4 v = make_float4(0.f, 0.f, 0.f, 0.f);
        int gn = n0 + n;
        if (gn < 4 * HH && kq < 100)
            v = tf32r4(*(const float4*)(Wnk + (long)gn * HH + k0 + kq));
        *(float4*)&Ws[n * WS_STRIDE + kq] = v;
    }
    __syncthreads();

    for (int s = 0; s < CL; s++) {
        const int ph = s & 1;
        const float* H = SH + (long)(dir * 2 + ph) * BB * HH;

        for (int idx4 = tid; idx4 < 928; idx4 += LTHREADS) {
            int m = idx4 / 29, kq = (idx4 % 29) * 4;
            float4 v = make_float4(0.f, 0.f, 0.f, 0.f);
            if (kq < 100)
                v = tf32r4(*(const float4*)(H + (long)m * HH + k0 + kq));
            *(float4*)&Xs[m * WS_STRIDE + kq] = v;
        }
        __syncthreads();

        float acc[4][4];
#pragma unroll
        for (int u = 0; u < 4; u++)
#pragma unroll
            for (int e = 0; e < 4; e++) acc[u][e] = 0.f;

#pragma unroll
        for (int kt = 0; kt < 7; kt++) {
#pragma unroll
            for (int kc = 0; kc < 2; kc++) {
                const int kb = kt * 16 + kc * 8 + lr;
                unsigned a[4], b[4][2];
                const float* pa = Ws + (wn + lq) * WS_STRIDE + kb;
                a[0] = __float_as_uint(pa[0]);
                a[1] = __float_as_uint(pa[8 * WS_STRIDE]);
                a[2] = __float_as_uint(pa[4]);
                a[3] = __float_as_uint(pa[8 * WS_STRIDE + 4]);
#pragma unroll
                for (int u = 0; u < 4; u++) {
                    const float* pb = Xs + (u * 8 + lq) * WS_STRIDE + kb;
                    b[u][0] = __float_as_uint(pb[0]);
                    b[u][1] = __float_as_uint(pb[4]);
                }
#pragma unroll
                for (int u = 0; u < 4; u++)
                    mma8(acc[u], a, b[u]);
            }
        }
        __syncthreads();

#pragma unroll
        for (int u = 0; u < 4; u++) {
            int nl = wn + lq;
            int m = u * 8 + lr * 2;
            Cs[m * 260 + nl]           = acc[u][0];
            Cs[(m + 1) * 260 + nl]     = acc[u][1];
            Cs[m * 260 + nl + 8]       = acc[u][2];
            Cs[(m + 1) * 260 + nl + 8] = acc[u][3];
        }
        __syncthreads();
#pragma unroll
        for (int l = 0; l < 4; l++) {
            int idx = tid + l * LTHREADS;
            int m = idx >> 6, nl4 = (idx & 63) * 4;
            if (n0 + nl4 < 4 * HH)
                *(float4*)(outP + (long)m * 4 * HH + n0 + nl4) = *(float4*)&Cs[m * 260 + nl4];
        }
        grid_sync_ptr(bcnt, bgen, LSTM_BLOCKS);

        for (int idx = bx * LTHREADS + tid; idx < 2 * BB * HH; idx += LSTM_BLOCKS * LTHREADS) {
            const int d2 = idx / (BB * HH);
            const int r2 = idx % (BB * HH);
            const int b = r2 / HH, j = r2 % HH;
            const int tt = d2 ? (CL - 1 - s) : s;
            float4 g4 = make_float4(0.f, 0.f, 0.f, 0.f);
#pragma unroll
            for (int kq = 0; kq < LKS; kq++) {
                const float4* P = (const float4*)(lpart + ((long)(d2 * LKS + kq) * BB + b) * 4 * HH);
                float4 p = P[j];
                g4.x += p.x; g4.y += p.y; g4.z += p.z; g4.w += p.w;
            }
            const float* xw = d2 ? xb : xf;
            const long xbs = ((long)b * CL + tt) * 4 * HH;
            float gi = g4.x + xw[xbs + j];
            float gf = g4.y + xw[xbs + HH + j];
            float gg = g4.z + xw[xbs + 2 * HH + j];
            float go = g4.w + xw[xbs + 3 * HH + j];
            float c = SC[(long)d2 * BB * HH + b * HH + j];
            c = sigf(gf) * c + sigf(gi) * tanhf(gg);
            float h = sigf(go) * tanhf(c);
            SC[(long)d2 * BB * HH + b * HH + j] = c;
            SH[(long)(d2 * 2 + (ph ^ 1)) * BB * HH + b * HH + j] = h;
            enc[((long)b * CL + tt) * 2 * HH + d2 * HH + j] = h;
        }
        grid_sync_ptr(bcnt, bgen, LSTM_BLOCKS);
    }
}

// ======= M=32 partial fp32 GEMM tile =======
#define PART_TILE(LOAD_A, LOAD_B, KSLICE, NTOT)                                     \
    {                                                                               \
        float acc[4][4];                                                            \
        _Pragma("unroll") for (int r = 0; r < 4; r++)                               \
        _Pragma("unroll") for (int g = 0; g < 4; g++) acc[r][g] = 0.f;              \
        for (int kt = 0; kt < (KSLICE); kt += 16) {                                 \
            _Pragma("unroll") for (int l = 0; l < 2; l++) {                         \
                int idx = tid + l * 256;                                            \
                int kk = idx >> 5; int nn = (idx & 31) * 4;                         \
                float4 v = make_float4(0.f, 0.f, 0.f, 0.f);                         \
                int kl = kt + kk;                                                   \
                if (kl < (KSLICE) && (n0 + nn) < (NTOT)) { int kg = k0 + kl; LOAD_B; } \
                *(float4*)&Bs[kk][nn] = v;                                          \
            }                                                                       \
            _Pragma("unroll") for (int l = 0; l < 2; l++) {                         \
                int idx = tid + l * 256;                                            \
                int r = idx >> 4; int kk = idx & 15;                                \
                float v = 0.f;                                                      \
                int kl = kt + kk;                                                   \
                if (kl < (KSLICE)) { int kg = k0 + kl; LOAD_A; }                    \
                As[r][kk] = v;                                                      \
            }                                                                       \
            __syncthreads();                                                        \
            _Pragma("unroll") for (int kq = 0; kq < 4; kq++) {                      \
                float4 a4[4];                                                       \
                _Pragma("unroll") for (int r = 0; r < 4; r++)                       \
                    a4[r] = *(const float4*)&As[ty * 4 + r][kq * 4];                \
                _Pragma("unroll") for (int kk = 0; kk < 4; kk++) {                  \
                    float4 b4 = *(const float4*)&Bs[kq * 4 + kk][tx * 4];           \
                    _Pragma("unroll") for (int r = 0; r < 4; r++) {                 \
                        float a = (kk == 0) ? a4[r].x : (kk == 1) ? a4[r].y         \
                                  : (kk == 2) ? a4[r].z : a4[r].w;                  \
                        acc[r][0] += a * b4.x; acc[r][1] += a * b4.y;               \
                        acc[r][2] += a * b4.z; acc[r][3] += a * b4.w;               \
                    }                                                               \
                }                                                                   \
            }                                                                       \
            __syncthreads();                                                        \
        }                                                                           \
        int nn = n0 + tx * 4;                                                       \
        if (nn < (NTOT)) {                                                          \
            _Pragma("unroll") for (int r = 0; r < 4; r++)                           \
                *(float4*)(outp + (long)(ty * 4 + r) * (NTOT) + nn) =               \
                    make_float4(acc[r][0], acc[r][1], acc[r][2], acc[r][3]);        \
        }                                                                           \
    }

// ---------------- decoder step kernels (per-step launches) ----------------
__global__ void dec_part(const float* __restrict__ hdin)
{
    __shared__ float Bs[16][128];
    __shared__ float As[32][16];
    const int tid = threadIdx.x;
    const int tx = tid & 31, ty = tid >> 5;
    const int jt = blockIdx.x, ks = blockIdx.y;
    const int n0 = jt * 128;
    const int k0 = ks * 200;
    float* outp = g_dpart + (long)ks * BB * 4 * HH;
    PART_TILE(v = (kg < HH) ? g_oprev[r * HH + kg] : hdin[r * HH + kg - HH],
              v = (kg < HH) ? *(const float4*)(g_wxo_t + (long)kg * 4 * HH + n0 + nn)
                            : *(const float4*)(g_whd_t + (long)(kg - HH) * 4 * HH + n0 + nn),
              200, 4 * HH)
}

__global__ void dec_combine(float* __restrict__ hdout, int t)
{
    int idx = blockIdx.x * 256 + threadIdx.x;
    if (idx >= BB * HH) return;
    const int b = idx / HH, j = idx % HH;
    const float4* P = (const float4*)g_dpart;
    float4 g4 = P[(long)b * HH + j];
#pragma unroll
    for (int kq = 1; kq < DKS; kq++) {
        float4 p = P[((long)kq * BB + b) * HH + j];
        g4.x += p.x; g4.y += p.y; g4.z += p.z; g4.w += p.w;
    }
    const long xb = ((long)b * QL + t) * 4 * HH;
    float gi = g4.x + g_qx[xb + j];
    float gf = g4.y + g_qx[xb + HH + j];
    float gg = g4.z + g_qx[xb + 2 * HH + j];
    float go = g4.w + g_qx[xb + 3 * HH + j];
    float c = g_cd[b * HH + j];
    c = sigf(gf) * c + sigf(gi) * tanhf(gg);
    g_cd[b * HH + j] = c;
    hdout[b * HH + j] = sigf(go) * tanhf(c);
}

// scores + masked softmax -> g_alpha[b][c]  (512 threads = 16 warps; R13 exact)
__global__ void attn_score(const float* __restrict__ hd, const int* __restrict__ cw)
{
    const int b = blockIdx.x;
    const int tid = threadIdx.x;
    __shared__ float sh_h[HH];
    __shared__ float sh_e[CL];
    __shared__ float sred[16];
    const int warp = tid >> 5, lane = tid & 31;

    for (int i = tid; i < HH; i += 512) sh_h[i] = hd[b * HH + i];
    __syncthreads();
    for (int c = warp; c < CL; c += 16) {
        const float* ep = g_encp + ((long)b * CL + c) * HH;
        float s = 0.f;
        for (int k = lane; k < HH; k += 32) s += sh_h[k] * ep[k];
        for (int o = 16; o; o >>= 1) s += __shfl_down_sync(0xffffffffu, s, o);
        if (!lane) sh_e[c] = (cw[b * CL + c] != 0) ? s : -1e30f;
    }
    __syncthreads();

    float m = -1e30f;
    for (int c = tid; c < CL; c += 512) m = fmaxf(m, sh_e[c]);
    for (int o = 16; o; o >>= 1) m = fmaxf(m, __shfl_xor_sync(0xffffffffu, m, o));
    if (!lane) sred[warp] = m;
    __syncthreads();
    if (tid == 0) {
        float v = sred[0];
        for (int w = 1; w < 16; w++) v = fmaxf(v, sred[w]);
        sred[0] = v;
    }
    __syncthreads();
    m = sred[0];
    __syncthreads();

    float s = 0.f;
    for (int c = tid; c < CL; c += 512) {
        float e = expf(sh_e[c] - m);
        sh_e[c] = e;
        s += e;
    }
    for (int o = 16; o; o >>= 1) s += __shfl_xor_sync(0xffffffffu, s, o);
    if (!lane) sred[warp] = s;
    __syncthreads();
    if (tid == 0) {
        float v = 0.f;
        for (int w = 0; w < 16; w++) v += sred[w];
        sred[0] = v;
    }
    __syncthreads();
    const float inv = 1.0f / sred[0];
    for (int c = tid; c < CL; c += 512)
        g_alpha[b * CL + c] = sh_e[c] * inv;
}

__global__ void attn_ctx()
{
    const int b = blockIdx.y;
    const int d = blockIdx.x * 256 + threadIdx.x;
    __shared__ float sal[CL];
    for (int c = threadIdx.x; c < CL; c += 256) sal[c] = g_alpha[b * CL + c];
    __syncthreads();
    if (d >= 2 * HH) return;
    const float* eb = g_enc + (long)b * CL * 2 * HH + d;
    float acc = 0.f;
#pragma unroll 8
    for (int c = 0; c < CL; c++) acc += sal[c] * eb[(long)c * 2 * HH];
    g_a[b * 2 * HH + d] = acc;
}

__global__ void comb_part(const float* __restrict__ hdnew, const float* __restrict__ Wcomb)
{
    __shared__ float Bs[16][128];
    __shared__ float As[32][16];
    const int tid = threadIdx.x;
    const int tx = tid & 31, ty = tid >> 5;
    const int jt = blockIdx.x, ks = blockIdx.y;
    const int n0 = jt * 128;
    const int k0 = ks * 75;
    float* outp = g_cpart + (long)ks * BB * HH;
    PART_TILE(v = (kg < HH) ? hdnew[r * HH + kg] : g_a[r * 2 * HH + kg - HH],
              v = *(const float4*)(Wcomb + (long)kg * HH + n0 + nn),
              75, HH)
}

__global__ void comb_combine(int t)
{
    int idx = blockIdx.x * 256 + threadIdx.x;
    if (idx >= BB * HH) return;
    const int b = idx / HH, j = idx % HH;
    float s = 0.f;
#pragma unroll
    for (int kq = 0; kq < CKS; kq++) s += g_cpart[((long)kq * BB + b) * HH + j];
    float O = tanhf(s);
    g_oprev[b * HH + j] = O;
    g_outs[((long)b * QL + t) * HH + j] = O;
}

// ---------------- h0/c0 projection + o_prev init ----------------
__global__ void h0c0_kernel(const float* __restrict__ Whi, const float* __restrict__ Wci)
{
    int idx = blockIdx.x * 256 + threadIdx.x;
    if (idx >= BB * HH) return;
    int b = idx / HH, j = idx % HH;
    const float* hf = g_stateH + 0 * BB * HH;
    const float* hb = g_stateH + 2 * BB * HH;
    const float* cf = g_stateC;
    const float* cb = g_stateC + BB * HH;
    float ah = 0.f, ac = 0.f;
    for (int k = 0; k < HH; k++) {
        ah += hf[b * HH + k] * Whi[k * HH + j];
        ac += cf[b * HH + k] * Wci[k * HH + j];
    }
    for (int k = 0; k < HH; k++) {
        ah += hb[b * HH + k] * Whi[(HH + k) * HH + j];
        ac += cb[b * HH + k] * Wci[(HH + k) * HH + j];
    }
    g_hd[0][idx] = ah;
    g_cd[idx] = ac;
    g_oprev[idx] = 0.f;
}

// ---------------- log-softmax over vocab, in place (R13 exact) --------------
__global__ void logsoftmax_kernel(float* __restrict__ x)
{
    const long base = (long)blockIdx.x * VOC;
    const int tid = threadIdx.x;
    __shared__ float sred[8];
    const int warp = tid >> 5, lane = tid & 31;

    float m = -1e30f;
    for (int i = tid; i < VOC; i += 256) m = fmaxf(m, x[base + i]);
    for (int o = 16; o; o >>= 1) m = fmaxf(m, __shfl_xor_sync(0xffffffffu, m, o));
    if (!lane) sred[warp] = m;
    __syncthreads();
    if (tid == 0) {
        float v = sred[0];
        for (int w = 1; w < 8; w++) v = fmaxf(v, sred[w]);
        sred[0] = v;
    }
    __syncthreads();
    m = sred[0];
    __syncthreads();

    float s = 0.f;
    for (int i = tid; i < VOC; i += 256) s += expf(x[base + i] - m);
    for (int o = 16; o; o >>= 1) s += __shfl_xor_sync(0xffffffffu, s, o);
    if (!lane) sred[warp] = s;
    __syncthreads();
    if (tid == 0) {
        float v = 0.f;
        for (int w = 0; w < 8; w++) v += sred[w];
        sred[0] = v;
    }
    __syncthreads();
    const float lse = m + logf(sred[0]);

    for (int i = tid; i < VOC; i += 256) x[base + i] -= lse;
}

// ---------------- launch ----------------
extern "C" void kernel_launch(void* const* d_in, const int* in_sizes, int n_in,
                              void* d_out, int out_size)
{
    (void)in_sizes; (void)n_in; (void)out_size;
    const int*   cw      = (const int*)  d_in[0];
    const int*   qw      = (const int*)  d_in[1];
    const float* W_emb   = (const float*)d_in[2];
    const float* emb_prj = (const float*)d_in[3];
    const float* Wx_f    = (const float*)d_in[4];
    const float* Wh_f    = (const float*)d_in[5];
    const float* b_f     = (const float*)d_in[6];
    const float* Wx_b    = (const float*)d_in[7];
    const float* Wh_b    = (const float*)d_in[8];
    const float* b_b     = (const float*)d_in[9];
    const float* Wh_init = (const float*)d_in[10];
    const float* Wc_init = (const float*)d_in[11];
    const float* Wx_d    = (const float*)d_in[12];
    const float* Wh_d    = (const float*)d_in[13];
    const float* b_d     = (const float*)d_in[14];
    const float* W_att   = (const float*)d_in[15];
    const float* W_comb  = (const float*)d_in[16];
    const float* W_gen   = (const float*)d_in[17];
    const float* b_gen   = (const float*)d_in[18];
    float* out = (float*)d_out;

    void *p_cemb, *p_qemb, *p_xwf, *p_xwb, *p_qx;
    void *p_whd, *p_wxo, *p_whfnk, *p_whbnk;
    void *p_embt, *p_wxft, *p_wxbt, *p_wxdqt, *p_watt;
    void *p_enc, *p_encp, *p_outs, *p_SH, *p_SC, *p_lpart;
    void *p_lcnt, *p_lgen, *p_hd;
    cudaGetSymbolAddress(&p_cemb,  g_cemb);
    cudaGetSymbolAddress(&p_qemb,  g_qemb);
    cudaGetSymbolAddress(&p_xwf,   g_xwf);
    cudaGetSymbolAddress(&p_xwb,   g_xwb);
    cudaGetSymbolAddress(&p_qx,    g_qx);
    cudaGetSymbolAddress(&p_whd,   g_whd_t);
    cudaGetSymbolAddress(&p_wxo,   g_wxo_t);
    cudaGetSymbolAddress(&p_whfnk, g_whf_nk);
    cudaGetSymbolAddress(&p_whbnk, g_whb_nk);
    cudaGetSymbolAddress(&p_embt,  g_embt);
    cudaGetSymbolAddress(&p_wxft,  g_wxft);
    cudaGetSymbolAddress(&p_wxbt,  g_wxbt);
    cudaGetSymbolAddress(&p_wxdqt, g_wxdqt);
    cudaGetSymbolAddress(&p_watt,  g_watt);
    cudaGetSymbolAddress(&p_enc,   g_enc);
    cudaGetSymbolAddress(&p_encp,  g_encp);
    cudaGetSymbolAddress(&p_outs,  g_outs);
    cudaGetSymbolAddress(&p_SH,    g_stateH);
    cudaGetSymbolAddress(&p_SC,    g_stateC);
    cudaGetSymbolAddress(&p_lpart, g_lpart2);
    cudaGetSymbolAddress(&p_lcnt,  g_lbar_cnt);
    cudaGetSymbolAddress(&p_lgen,  g_lbar_genw);
    cudaGetSymbolAddress(&p_hd,    g_hd);
    float* hd0 = (float*)p_hd;
    float* hd1 = hd0 + BB * HH;

    cudaFuncSetAttribute(lstm_persist, cudaFuncAttributeMaxDynamicSharedMemorySize,
                         LSTM_SMEM_BYTES);

    zero_state_kernel<<<300, 256>>>();
    transpose_t<<<dim3(19, 10), dim3(32, 8)>>>(emb_prj, (float*)p_embt, EMB, HH, HH);
    transpose_t<<<dim3(75, 19), dim3(32, 8)>>>(Wx_f, (float*)p_wxft, HH, 4 * HH, 4 * HH);
    gemm_tf32<<<dim3(5, 200), 256>>>(W_emb, cw, (float*)p_embt, nullptr,
                                     (float*)p_cemb, BB * CL, HH, EMB);            // ncu window
    gemm_tf32<<<dim3(19, 200), 256>>>((float*)p_cemb, nullptr, (float*)p_wxft, b_f,
                                      (float*)p_xwf, BB * CL, 4 * HH, HH);
    transpose_t<<<dim3(75, 19), dim3(32, 8)>>>(Wx_b, (float*)p_wxbt, HH, 4 * HH, 4 * HH);
    gemm_tf32<<<dim3(19, 200), 256>>>((float*)p_cemb, nullptr, (float*)p_wxbt, b_b,
                                      (float*)p_xwb, BB * CL, 4 * HH, HH);
    gemm_tf32<<<dim3(5, 15), 256>>>(W_emb, qw, (float*)p_embt, nullptr,
                                    (float*)p_qemb, BB * QL, HH, EMB);
    transpose_t<<<dim3(75, 19), dim3(32, 8)>>>(Wx_d, (float*)p_wxdqt, HH, 4 * HH, 4 * HH);
    gemm_tf32<<<dim3(19, 15), 256>>>((float*)p_qemb, nullptr, (float*)p_wxdqt, b_d,
                                     (float*)p_qx, BB * QL, 4 * HH, HH);
    transpose_gates_nk<<<5625, 256>>>(Wh_f, (float*)p_whfnk);
    transpose_gates_nk<<<5625, 256>>>(Wh_b, (float*)p_whbnk);
    transpose_gates<<<1407, 256>>>(Wh_d, (float*)p_whd);
    transpose_gates<<<1407, 256>>>(Wx_d + HH * 4 * HH, (float*)p_wxo);

    // persistent BiLSTM (512 threads; ~3.5 ms measured)
    lstm_persist<<<LSTM_BLOCKS, LTHREADS, LSTM_SMEM_BYTES>>>(
        (const float*)p_whfnk, (const float*)p_whbnk,
        (const float*)p_xwf, (const float*)p_xwb,
        (float*)p_SH, (float*)p_SC, (float*)p_enc, (float*)p_lpart,
        (unsigned*)p_lcnt, (unsigned*)p_lgen);

    h0c0_kernel<<<75, 256>>>(Wh_init, Wc_init);
    transpose_t<<<dim3(19, 38), dim3(32, 8)>>>(W_att, (float*)p_watt, 2 * HH, HH, HH);
    gemm_tf32<<<dim3(5, 200), 256>>>((float*)p_enc, nullptr, (float*)p_watt, nullptr,
                                     (float*)p_encp, BB * CL, HH, 2 * HH);

    // decoder: per-step launches (graph edges do the sync)
    for (int t = 0; t < QL; t++) {
        const float* hin = (t & 1) ? hd1 : hd0;
        float* hout      = (t & 1) ? hd0 : hd1;
        dec_part<<<dim3(19, DKS), 256>>>(hin);
        dec_combine<<<75, 256>>>(hout, t);
        attn_score<<<BB, 512>>>(hout, cw);
        attn_ctx<<<dim3(5, BB), 256>>>();
        comb_part<<<dim3(5, CKS), 256>>>(hout, W_comb);
        comb_combine<<<75, 256>>>(t);
    }

    // vocab projection directly from W_gen[K][N] (no 120 MB transpose)
    gemm_tf32_bn<<<dim3(391, 15), 256>>>((float*)p_outs, W_gen, b_gen,
                                         out, BB * QL, VOC, HH);
    logsoftmax_kernel<<<BB * QL, 256>>>(out);
}

// round 16
// speedup vs baseline: 1.0719x; 1.0136x over previous
#include <cuda_runtime.h>
#include <math.h>

#define BB 32
#define CL 400
#define QL 30
#define HH 600
#define VOC 50000
#define EMB 300

#define LKS 6    // lstm k-split (kslice 100, padded to 112)
#define DKS 6    // decoder k-split (K=1200, kslice 200)
#define CKS 24   // comb k-split (K=1800, kslice 75)

#define LSTM_BLOCKS 120   // 10 n-tiles x LKS x 2 dirs
#define LTHREADS 512      // 16 warps

#define WS_STRIDE 116
#define WS_FLOATS (256 * WS_STRIDE)   // 29696
#define XC_FLOATS (32 * 260)          // 8320
#define LSTM_SMEM_BYTES ((WS_FLOATS + XC_FLOATS) * 4)   // 152064

// ---------------- scratch (device globals; allocation-free) ----------------
__device__ float g_cemb[BB*CL*HH];
__device__ float g_qemb[BB*QL*HH];
__device__ float g_xwf [BB*CL*4*HH];        // plain gate-blocked x-parts [row][g*600+j]
__device__ float g_xwb [BB*CL*4*HH];
__device__ float g_qx  [BB*QL*4*HH];
__device__ float g_whd_t[HH*HH*4];          // [k][j*4+g]
__device__ float g_wxo_t[HH*HH*4];
__device__ float g_whf_nk[4*HH*HH];         // [n=j*4+g][k]
__device__ float g_whb_nk[4*HH*HH];
__device__ float g_enc [BB*CL*2*HH];
__device__ float g_encp[BB*CL*HH];
__device__ float g_stateH[2*2*BB*HH];       // [dir][phase][b][j]
__device__ float g_stateC[2*BB*HH];
__device__ float g_hd[2][BB*HH];
__device__ float g_cd[BB*HH];
__device__ float g_oprev[BB*HH];
__device__ float g_alpha[BB*CL];
__device__ float g_a[BB*2*HH];
__device__ float g_outs[BB*QL*HH];
__device__ float g_lpart2[2*LKS*BB*4*HH];
__device__ float g_dpart[DKS*BB*4*HH];
__device__ float g_cpart[CKS*BB*HH];

// LSTM barrier: cnt and gen on separate 128B lines
__device__ __align__(128) unsigned g_lbar_cnt[32];
__device__ __align__(128) unsigned g_lbar_genw[32];

__device__ __forceinline__ void grid_sync_ptr(unsigned* cnt, volatile unsigned* gen, unsigned nb)
{
    __syncthreads();
    if (threadIdx.x == 0) {
        unsigned g = *gen;
        __threadfence();
        if (atomicAdd(cnt, 1u) == nb - 1u) {
            *cnt = 0u;
            __threadfence();
            *gen = g + 1u;
        } else {
            while (*gen == g) { }
            __threadfence();
        }
    }
    __syncthreads();
}

__device__ __forceinline__ float sigf(float x) { return 1.0f / (1.0f + expf(-x)); }

__device__ __forceinline__ float tf32r(float f)
{
    unsigned u; asm("cvt.rna.tf32.f32 %0, %1;" : "=r"(u) : "f"(f));
    return __uint_as_float(u);
}
__device__ __forceinline__ float4 tf32r4(float4 v)
{
    return make_float4(tf32r(v.x), tf32r(v.y), tf32r(v.z), tf32r(v.w));
}
__device__ __forceinline__ void mma8(float* d, const unsigned* a, const unsigned* b)
{
    asm volatile("mma.sync.aligned.m16n8k8.row.col.f32.tf32.tf32.f32 "
        "{%0,%1,%2,%3}, {%4,%5,%6,%7}, {%8,%9}, {%0,%1,%2,%3};"
        : "+f"(d[0]), "+f"(d[1]), "+f"(d[2]), "+f"(d[3])
        : "r"(a[0]), "r"(a[1]), "r"(a[2]), "r"(a[3]), "r"(b[0]), "r"(b[1]));
}

__device__ __forceinline__ unsigned smem_u32p(const void* p)
{
    return (unsigned)__cvta_generic_to_shared(p);
}
__device__ __forceinline__ void cpa16(unsigned dst, const void* src, int bytes)
{
    asm volatile("cp.async.cg.shared.global [%0], [%1], 16, %2;"
                 :: "r"(dst), "l"(src), "r"(bytes) : "memory");
}

// ---------------- tf32 GEMM (B natural layout + optional row gather) --------
// C[M][N] = gather(X)[M][K] @ W[K][N]. W rows n-contiguous (no pre-transpose).
// Smem W tile [16][136]: bank = lr*8+lq (+const) -> conflict-free fragments.
// Requires N % 4 == 0 (true for 600/1200/2400/50000).
__global__ void gemm_tf32_bn(const float* __restrict__ X, const int* __restrict__ gidx,
                             const float* __restrict__ W, const float* __restrict__ bias,
                             float* __restrict__ C, int M, int N, int K)
{
    __shared__ float smem[8448];    // Wk[2]:2x2176 (=4352), Xs[2]:2x1280 (6912); Cs overlay
    float* WkB[2] = { smem, smem + 2176 };
    float* XsB[2] = { smem + 4352, smem + 5632 };
    const int tid = threadIdx.x;
    const int warp = tid >> 5, lane = tid & 31;
    const int lq = lane >> 2, lr = lane & 3;
    const int wn = (warp & 3) * 32, wm = (warp >> 2) * 32;
    const int bn0 = blockIdx.x * 128;
    const int bm0 = blockIdx.y * 64;

    // W copy descriptors: 512 float4 per stage, 2 per thread
    const int wk0 = tid >> 5;               // k row 0..7
    const int wk1 = 8 + (tid >> 5);         // k row 8..15
    const int wn4 = (tid & 31) * 4;
    const int gw_n = bn0 + wn4;
    const int wvalid = (gw_n < N);          // N % 4 == 0: float4 all-in or all-out

    // X copy descriptors (optional gather)
    const int kqx = (tid & 3) * 4;
    const int m_x = tid >> 2;
    const float* rowX = nullptr;
    if (bm0 + m_x < M)
        rowX = X + (gidx ? (long)gidx[bm0 + m_x] * K : (long)(bm0 + m_x) * K);

    unsigned wka0[2], wka1[2], xsa[2];
#pragma unroll
    for (int b = 0; b < 2; b++) {
        wka0[b] = smem_u32p(&WkB[b][wk0 * 136 + wn4]);
        wka1[b] = smem_u32p(&WkB[b][wk1 * 136 + wn4]);
        xsa[b]  = smem_u32p(&XsB[b][m_x * 20 + kqx]);
    }

    const int KT = (K + 15) / 16;

#define GB_ISSUE(KT0, BUF) do {                                             \
        int kx_ = (KT0) * 16 + kqx;                                         \
        int bx_ = (rowX && kx_ < K) ? 16 : 0;                               \
        int kr0_ = (KT0) * 16 + wk0;                                        \
        int kr1_ = (KT0) * 16 + wk1;                                        \
        int b0_ = (wvalid && kr0_ < K) ? 16 : 0;                            \
        int b1_ = (wvalid && kr1_ < K) ? 16 : 0;                            \
        cpa16(wka0[BUF], b0_ ? W + (long)kr0_ * N + gw_n : W, b0_);         \
        cpa16(wka1[BUF], b1_ ? W + (long)kr1_ * N + gw_n : W, b1_);         \
        cpa16(xsa[BUF],  bx_ ? rowX + kx_ : W, bx_);                        \
        asm volatile("cp.async.commit_group;" ::: "memory");                \
    } while (0)

    float acc[2][4][4];
#pragma unroll
    for (int t = 0; t < 2; t++)
#pragma unroll
        for (int u = 0; u < 4; u++)
#pragma unroll
            for (int e = 0; e < 4; e++) acc[t][u][e] = 0.f;

    GB_ISSUE(0, 0);
    for (int kt = 0; kt < KT; kt++) {
        if (kt + 1 < KT) {
            GB_ISSUE(kt + 1, (kt + 1) & 1);
            asm volatile("cp.async.wait_group 1;" ::: "memory");
        } else {
            asm volatile("cp.async.wait_group 0;" ::: "memory");
        }
        __syncthreads();

        const float* Wk = WkB[kt & 1];
        const float* Xs = XsB[kt & 1];
#pragma unroll
        for (int kc = 0; kc < 2; kc++) {
            const int kb = kc * 8 + lr;
            unsigned a[2][4], b[4][2];
#pragma unroll
            for (int t = 0; t < 2; t++) {
                const float* p = Wk + kb * 136 + wn + t * 16 + lq;
                a[t][0] = __float_as_uint(p[0]);
                a[t][1] = __float_as_uint(p[8]);
                a[t][2] = __float_as_uint(p[4 * 136]);
                a[t][3] = __float_as_uint(p[4 * 136 + 8]);
            }
#pragma unroll
            for (int u = 0; u < 4; u++) {
                const float* p = Xs + (wm + u * 8 + lq) * 20 + kb;
                b[u][0] = __float_as_uint(p[0]);
                b[u][1] = __float_as_uint(p[4]);
            }
#pragma unroll
            for (int t = 0; t < 2; t++)
#pragma unroll
                for (int u = 0; u < 4; u++)
                    mma8(acc[t][u], a[t], b[u]);
        }
        __syncthreads();
    }
#undef GB_ISSUE

    float* Cs = smem;
#pragma unroll
    for (int t = 0; t < 2; t++)
#pragma unroll
        for (int u = 0; u < 4; u++) {
            int nl = wn + t * 16 + lq;
            int m = wm + u * 8 + lr * 2;
            Cs[m * 132 + nl]           = acc[t][u][0];
            Cs[(m + 1) * 132 + nl]     = acc[t][u][1];
            Cs[m * 132 + nl + 8]       = acc[t][u][2];
            Cs[(m + 1) * 132 + nl + 8] = acc[t][u][3];
        }
    __syncthreads();
#pragma unroll
    for (int l = 0; l < 8; l++) {
        int idx = tid + l * 256;
        int m = idx >> 5, nl4 = (idx & 31) * 4;
        int gm = bm0 + m, gn = bn0 + nl4;
        if (gm < M && gn < N) {
            float4 v = *(float4*)&Cs[m * 132 + nl4];
            if (bias) {
                v.x += bias[gn]; v.y += bias[gn + 1];
                v.z += bias[gn + 2]; v.w += bias[gn + 3];
            }
            *(float4*)(C + (long)gm * N + gn) = v;
        }
    }
}

// ---------------- small helpers ----------------
__global__ void zero_state_kernel()
{
    int i = blockIdx.x * 256 + threadIdx.x;
    if (i < 2 * 2 * BB * HH) g_stateH[i] = 0.f;
    if (i < 2 * BB * HH)     g_stateC[i] = 0.f;
    if (i < 32) { g_lbar_cnt[i] = 0u; g_lbar_genw[i] = 0u; }
}

__global__ void transpose_gates(const float* __restrict__ W, float* __restrict__ Wt)
{
    int idx = blockIdx.x * 256 + threadIdx.x;
    if (idx >= HH * HH) return;
    int k = idx / HH, j = idx % HH;
    float4 v;
    v.x = W[k * 4 * HH + j];
    v.y = W[k * 4 * HH + HH + j];
    v.z = W[k * 4 * HH + 2 * HH + j];
    v.w = W[k * 4 * HH + 3 * HH + j];
    ((float4*)Wt)[idx] = v;
}

__global__ void transpose_gates_nk(const float* __restrict__ W, float* __restrict__ out)
{
    long idx = (long)blockIdx.x * 256 + threadIdx.x;
    if (idx >= (long)4 * HH * HH) return;
    int n = (int)(idx / HH), k = (int)(idx % HH);
    out[idx] = W[(long)k * 4 * HH + (n & 3) * HH + (n >> 2)];
}

// ---------------- persistent BiLSTM: 512 threads, weights smem-resident -----
__global__ void lstm_persist(const float* __restrict__ Wf, const float* __restrict__ Wb,
                             const float* __restrict__ xf, const float* __restrict__ xb,
                             float* __restrict__ SH, float* __restrict__ SC,
                             float* __restrict__ enc, float* __restrict__ lpart,
                             unsigned* bcnt, unsigned* bgenw)
{
    extern __shared__ float dsm[];
    float* Ws = dsm;
    float* Xs = dsm + WS_FLOATS;
    float* Cs = dsm + WS_FLOATS;

    const int bx = blockIdx.x;
    const int tid = threadIdx.x;
    const int warp = tid >> 5, lane = tid & 31;
    const int lq = lane >> 2, lr = lane & 3;
    const int nb = bx % 10;
    const int ks = (bx / 10) % LKS;
    const int dir = bx / (10 * LKS);
    const int n0 = nb * 256;
    const int k0 = ks * 100;
    const int wn = warp * 16;
    const float* Wnk = dir ? Wb : Wf;
    float* outP = lpart + (long)(dir * LKS + ks) * BB * 4 * HH;
    volatile unsigned* bgen = (volatile unsigned*)bgenw;

    for (int idx4 = tid; idx4 < 256 * 29; idx4 += LTHREADS) {
        int n = idx4 / 29, kq = (idx4 % 29) * 4;
        float4 v = make_float4(0.f, 0.f, 0.f, 0.f);
        int gn = n0 + n;
        if (gn < 4 * HH && kq < 100)
            v = tf32r4(*(const float4*)(Wnk + (long)gn * HH + k0 + kq));
        *(float4*)&Ws[n * WS_STRIDE + kq] = v;
    }
    __syncthreads();

    for (int s = 0; s < CL; s++) {
        const int ph = s & 1;
        const float* H = SH + (long)(dir * 2 + ph) * BB * HH;

        for (int idx4 = tid; idx4 < 928; idx4 += LTHREADS) {
            int m = idx4 / 29, kq = (idx4 % 29) * 4;
            float4 v = make_float4(0.f, 0.f, 0.f, 0.f);
            if (kq < 100)
                v = tf32r4(*(const float4*)(H + (long)m * HH + k0 + kq));
            *(float4*)&Xs[m * WS_STRIDE + kq] = v;
        }
        __syncthreads();

        float acc[4][4];
#pragma unroll
        for (int u = 0; u < 4; u++)
#pragma unroll
            for (int e = 0; e < 4; e++) acc[u][e] = 0.f;

#pragma unroll
        for (int kt = 0; kt < 7; kt++) {
#pragma unroll
            for (int kc = 0; kc < 2; kc++) {
                const int kb = kt * 16 + kc * 8 + lr;
                unsigned a[4], b[4][2];
                const float* pa = Ws + (wn + lq) * WS_STRIDE + kb;
                a[0] = __float_as_uint(pa[0]);
                a[1] = __float_as_uint(pa[8 * WS_STRIDE]);
                a[2] = __float_as_uint(pa[4]);
                a[3] = __float_as_uint(pa[8 * WS_STRIDE + 4]);
#pragma unroll
                for (int u = 0; u < 4; u++) {
                    const float* pb = Xs + (u * 8 + lq) * WS_STRIDE + kb;
                    b[u][0] = __float_as_uint(pb[0]);
                    b[u][1] = __float_as_uint(pb[4]);
                }
#pragma unroll
                for (int u = 0; u < 4; u++)
                    mma8(acc[u], a, b[u]);
            }
        }
        __syncthreads();

#pragma unroll
        for (int u = 0; u < 4; u++) {
            int nl = wn + lq;
            int m = u * 8 + lr * 2;
            Cs[m * 260 + nl]           = acc[u][0];
            Cs[(m + 1) * 260 + nl]     = acc[u][1];
            Cs[m * 260 + nl + 8]       = acc[u][2];
            Cs[(m + 1) * 260 + nl + 8] = acc[u][3];
        }
        __syncthreads();
#pragma unroll
        for (int l = 0; l < 4; l++) {
            int idx = tid + l * LTHREADS;
            int m = idx >> 6, nl4 = (idx & 63) * 4;
            if (n0 + nl4 < 4 * HH)
                *(float4*)(outP + (long)m * 4 * HH + n0 + nl4) = *(float4*)&Cs[m * 260 + nl4];
        }
        grid_sync_ptr(bcnt, bgen, LSTM_BLOCKS);

        for (int idx = bx * LTHREADS + tid; idx < 2 * BB * HH; idx += LSTM_BLOCKS * LTHREADS) {
            const int d2 = idx / (BB * HH);
            const int r2 = idx % (BB * HH);
            const int b = r2 / HH, j = r2 % HH;
            const int tt = d2 ? (CL - 1 - s) : s;
            float4 g4 = make_float4(0.f, 0.f, 0.f, 0.f);
#pragma unroll
            for (int kq = 0; kq < LKS; kq++) {
                const float4* P = (const float4*)(lpart + ((long)(d2 * LKS + kq) * BB + b) * 4 * HH);
                float4 p = P[j];
                g4.x += p.x; g4.y += p.y; g4.z += p.z; g4.w += p.w;
            }
            const float* xw = d2 ? xb : xf;
            const long xbs = ((long)b * CL + tt) * 4 * HH;
            float gi = g4.x + xw[xbs + j];
            float gf = g4.y + xw[xbs + HH + j];
            float gg = g4.z + xw[xbs + 2 * HH + j];
            float go = g4.w + xw[xbs + 3 * HH + j];
            float c = SC[(long)d2 * BB * HH + b * HH + j];
            c = sigf(gf) * c + sigf(gi) * tanhf(gg);
            float h = sigf(go) * tanhf(c);
            SC[(long)d2 * BB * HH + b * HH + j] = c;
            SH[(long)(d2 * 2 + (ph ^ 1)) * BB * HH + b * HH + j] = h;
            enc[((long)b * CL + tt) * 2 * HH + d2 * HH + j] = h;
        }
        grid_sync_ptr(bcnt, bgen, LSTM_BLOCKS);
    }
}

// ======= M=32 partial fp32 GEMM tile =======
#define PART_TILE(LOAD_A, LOAD_B, KSLICE, NTOT)                                     \
    {                                                                               \
        float acc[4][4];                                                            \
        _Pragma("unroll") for (int r = 0; r < 4; r++)                               \
        _Pragma("unroll") for (int g = 0; g < 4; g++) acc[r][g] = 0.f;              \
        for (int kt = 0; kt < (KSLICE); kt += 16) {                                 \
            _Pragma("unroll") for (int l = 0; l < 2; l++) {                         \
                int idx = tid + l * 256;                                            \
                int kk = idx >> 5; int nn = (idx & 31) * 4;                         \
                float4 v = make_float4(0.f, 0.f, 0.f, 0.f);                         \
                int kl = kt + kk;                                                   \
                if (kl < (KSLICE) && (n0 + nn) < (NTOT)) { int kg = k0 + kl; LOAD_B; } \
                *(float4*)&Bs[kk][nn] = v;                                          \
            }                                                                       \
            _Pragma("unroll") for (int l = 0; l < 2; l++) {                         \
                int idx = tid + l * 256;                                            \
                int r = idx >> 4; int kk = idx & 15;                                \
                float v = 0.f;                                                      \
                int kl = kt + kk;                                                   \
                if (kl < (KSLICE)) { int kg = k0 + kl; LOAD_A; }                    \
                As[r][kk] = v;                                                      \
            }                                                                       \
            __syncthreads();                                                        \
            _Pragma("unroll") for (int kq = 0; kq < 4; kq++) {                      \
                float4 a4[4];                                                       \
                _Pragma("unroll") for (int r = 0; r < 4; r++)                       \
                    a4[r] = *(const float4*)&As[ty * 4 + r][kq * 4];                \
                _Pragma("unroll") for (int kk = 0; kk < 4; kk++) {                  \
                    float4 b4 = *(const float4*)&Bs[kq * 4 + kk][tx * 4];           \
                    _Pragma("unroll") for (int r = 0; r < 4; r++) {                 \
                        float a = (kk == 0) ? a4[r].x : (kk == 1) ? a4[r].y         \
                                  : (kk == 2) ? a4[r].z : a4[r].w;                  \
                        acc[r][0] += a * b4.x; acc[r][1] += a * b4.y;               \
                        acc[r][2] += a * b4.z; acc[r][3] += a * b4.w;               \
                    }                                                               \
                }                                                                   \
            }                                                                       \
            __syncthreads();                                                        \
        }                                                                           \
        int nn = n0 + tx * 4;                                                       \
        if (nn < (NTOT)) {                                                          \
            _Pragma("unroll") for (int r = 0; r < 4; r++)                           \
                *(float4*)(outp + (long)(ty * 4 + r) * (NTOT) + nn) =               \
                    make_float4(acc[r][0], acc[r][1], acc[r][2], acc[r][3]);        \
        }                                                                           \
    }

// ---------------- decoder step kernels (per-step launches) ----------------
__global__ void dec_part(const float* __restrict__ hdin)
{
    __shared__ float Bs[16][128];
    __shared__ float As[32][16];
    const int tid = threadIdx.x;
    const int tx = tid & 31, ty = tid >> 5;
    const int jt = blockIdx.x, ks = blockIdx.y;
    const int n0 = jt * 128;
    const int k0 = ks * 200;
    float* outp = g_dpart + (long)ks * BB * 4 * HH;
    PART_TILE(v = (kg < HH) ? g_oprev[r * HH + kg] : hdin[r * HH + kg - HH],
              v = (kg < HH) ? *(const float4*)(g_wxo_t + (long)kg * 4 * HH + n0 + nn)
                            : *(const float4*)(g_whd_t + (long)(kg - HH) * 4 * HH + n0 + nn),
              200, 4 * HH)
}

__global__ void dec_combine(float* __restrict__ hdout, int t)
{
    int idx = blockIdx.x * 256 + threadIdx.x;
    if (idx >= BB * HH) return;
    const int b = idx / HH, j = idx % HH;
    const float4* P = (const float4*)g_dpart;
    float4 g4 = P[(long)b * HH + j];
#pragma unroll
    for (int kq = 1; kq < DKS; kq++) {
        float4 p = P[((long)kq * BB + b) * HH + j];
        g4.x += p.x; g4.y += p.y; g4.z += p.z; g4.w += p.w;
    }
    const long xb = ((long)b * QL + t) * 4 * HH;
    float gi = g4.x + g_qx[xb + j];
    float gf = g4.y + g_qx[xb + HH + j];
    float gg = g4.z + g_qx[xb + 2 * HH + j];
    float go = g4.w + g_qx[xb + 3 * HH + j];
    float c = g_cd[b * HH + j];
    c = sigf(gf) * c + sigf(gi) * tanhf(gg);
    g_cd[b * HH + j] = c;
    hdout[b * HH + j] = sigf(go) * tanhf(c);
}

// scores + masked softmax -> g_alpha[b][c]  (512 threads = 16 warps)
__global__ void attn_score(const float* __restrict__ hd, const int* __restrict__ cw)
{
    const int b = blockIdx.x;
    const int tid = threadIdx.x;
    __shared__ float sh_h[HH];
    __shared__ float sh_e[CL];
    __shared__ float sred[16];
    const int warp = tid >> 5, lane = tid & 31;

    for (int i = tid; i < HH; i += 512) sh_h[i] = hd[b * HH + i];
    __syncthreads();
    for (int c = warp; c < CL; c += 16) {
        const float* ep = g_encp + ((long)b * CL + c) * HH;
        float s = 0.f;
        for (int k = lane; k < HH; k += 32) s += sh_h[k] * ep[k];
        for (int o = 16; o; o >>= 1) s += __shfl_down_sync(0xffffffffu, s, o);
        if (!lane) sh_e[c] = (cw[b * CL + c] != 0) ? s : -1e30f;
    }
    __syncthreads();

    float m = -1e30f;
    for (int c = tid; c < CL; c += 512) m = fmaxf(m, sh_e[c]);
    for (int o = 16; o; o >>= 1) m = fmaxf(m, __shfl_xor_sync(0xffffffffu, m, o));
    if (!lane) sred[warp] = m;
    __syncthreads();
    if (tid == 0) {
        float v = sred[0];
        for (int w = 1; w < 16; w++) v = fmaxf(v, sred[w]);
        sred[0] = v;
    }
    __syncthreads();
    m = sred[0];
    __syncthreads();

    float s = 0.f;
    for (int c = tid; c < CL; c += 512) {
        float e = expf(sh_e[c] - m);
        sh_e[c] = e;
        s += e;
    }
    for (int o = 16; o; o >>= 1) s += __shfl_xor_sync(0xffffffffu, s, o);
    if (!lane) sred[warp] = s;
    __syncthreads();
    if (tid == 0) {
        float v = 0.f;
        for (int w = 0; w < 16; w++) v += sred[w];
        sred[0] = v;
    }
    __syncthreads();
    const float inv = 1.0f / sred[0];
    for (int c = tid; c < CL; c += 512)
        g_alpha[b * CL + c] = sh_e[c] * inv;
}

__global__ void attn_ctx()
{
    const int b = blockIdx.y;
    const int d = blockIdx.x * 256 + threadIdx.x;
    __shared__ float sal[CL];
    for (int c = threadIdx.x; c < CL; c += 256) sal[c] = g_alpha[b * CL + c];
    __syncthreads();
    if (d >= 2 * HH) return;
    const float* eb = g_enc + (long)b * CL * 2 * HH + d;
    float acc = 0.f;
#pragma unroll 8
    for (int c = 0; c < CL; c++) acc += sal[c] * eb[(long)c * 2 * HH];
    g_a[b * 2 * HH + d] = acc;
}

__global__ void comb_part(const float* __restrict__ hdnew, const float* __restrict__ Wcomb)
{
    __shared__ float Bs[16][128];
    __shared__ float As[32][16];
    const int tid = threadIdx.x;
    const int tx = tid & 31, ty = tid >> 5;
    const int jt = blockIdx.x, ks = blockIdx.y;
    const int n0 = jt * 128;
    const int k0 = ks * 75;
    float* outp = g_cpart + (long)ks * BB * HH;
    PART_TILE(v = (kg < HH) ? hdnew[r * HH + kg] : g_a[r * 2 * HH + kg - HH],
              v = *(const float4*)(Wcomb + (long)kg * HH + n0 + nn),
              75, HH)
}

__global__ void comb_combine(int t)
{
    int idx = blockIdx.x * 256 + threadIdx.x;
    if (idx >= BB * HH) return;
    const int b = idx / HH, j = idx % HH;
    float s = 0.f;
#pragma unroll
    for (int kq = 0; kq < CKS; kq++) s += g_cpart[((long)kq * BB + b) * HH + j];
    float O = tanhf(s);
    g_oprev[b * HH + j] = O;
    g_outs[((long)b * QL + t) * HH + j] = O;
}

// ---------------- h0/c0 projection + o_prev init ----------------
__global__ void h0c0_kernel(const float* __restrict__ Whi, const float* __restrict__ Wci)
{
    int idx = blockIdx.x * 256 + threadIdx.x;
    if (idx >= BB * HH) return;
    int b = idx / HH, j = idx % HH;
    const float* hf = g_stateH + 0 * BB * HH;
    const float* hb = g_stateH + 2 * BB * HH;
    const float* cf = g_stateC;
    const float* cb = g_stateC + BB * HH;
    float ah = 0.f, ac = 0.f;
    for (int k = 0; k < HH; k++) {
        ah += hf[b * HH + k] * Whi[k * HH + j];
        ac += cf[b * HH + k] * Wci[k * HH + j];
    }
    for (int k = 0; k < HH; k++) {
        ah += hb[b * HH + k] * Whi[(HH + k) * HH + j];
        ac += cb[b * HH + k] * Wci[(HH + k) * HH + j];
    }
    g_hd[0][idx] = ah;
    g_cd[idx] = ac;
    g_oprev[idx] = 0.f;
}

// ---------------- log-softmax over vocab, in place ----------------
__global__ void logsoftmax_kernel(float* __restrict__ x)
{
    const long base = (long)blockIdx.x * VOC;
    const int tid = threadIdx.x;
    __shared__ float sred[8];
    const int warp = tid >> 5, lane = tid & 31;

    float m = -1e30f;
    for (int i = tid; i < VOC; i += 256) m = fmaxf(m, x[base + i]);
    for (int o = 16; o; o >>= 1) m = fmaxf(m, __shfl_xor_sync(0xffffffffu, m, o));
    if (!lane) sred[warp] = m;
    __syncthreads();
    if (tid == 0) {
        float v = sred[0];
        for (int w = 1; w < 8; w++) v = fmaxf(v, sred[w]);
        sred[0] = v;
    }
    __syncthreads();
    m = sred[0];
    __syncthreads();

    float s = 0.f;
    for (int i = tid; i < VOC; i += 256) s += expf(x[base + i] - m);
    for (int o = 16; o; o >>= 1) s += __shfl_xor_sync(0xffffffffu, s, o);
    if (!lane) sred[warp] = s;
    __syncthreads();
    if (tid == 0) {
        float v = 0.f;
        for (int w = 0; w < 8; w++) v += sred[w];
        sred[0] = v;
    }
    __syncthreads();
    const float lse = m + logf(sred[0]);

    for (int i = tid; i < VOC; i += 256) x[base + i] -= lse;
}

// ---------------- launch ----------------
extern "C" void kernel_launch(void* const* d_in, const int* in_sizes, int n_in,
                              void* d_out, int out_size)
{
    (void)in_sizes; (void)n_in; (void)out_size;
    const int*   cw      = (const int*)  d_in[0];
    const int*   qw      = (const int*)  d_in[1];
    const float* W_emb   = (const float*)d_in[2];
    const float* emb_prj = (const float*)d_in[3];
    const float* Wx_f    = (const float*)d_in[4];
    const float* Wh_f    = (const float*)d_in[5];
    const float* b_f     = (const float*)d_in[6];
    const float* Wx_b    = (const float*)d_in[7];
    const float* Wh_b    = (const float*)d_in[8];
    const float* b_b     = (const float*)d_in[9];
    const float* Wh_init = (const float*)d_in[10];
    const float* Wc_init = (const float*)d_in[11];
    const float* Wx_d    = (const float*)d_in[12];
    const float* Wh_d    = (const float*)d_in[13];
    const float* b_d     = (const float*)d_in[14];
    const float* W_att   = (const float*)d_in[15];
    const float* W_comb  = (const float*)d_in[16];
    const float* W_gen   = (const float*)d_in[17];
    const float* b_gen   = (const float*)d_in[18];
    float* out = (float*)d_out;

    void *p_cemb, *p_qemb, *p_xwf, *p_xwb, *p_qx;
    void *p_whd, *p_wxo, *p_whfnk, *p_whbnk;
    void *p_enc, *p_encp, *p_outs, *p_SH, *p_SC, *p_lpart;
    void *p_lcnt, *p_lgen, *p_hd;
    cudaGetSymbolAddress(&p_cemb,  g_cemb);
    cudaGetSymbolAddress(&p_qemb,  g_qemb);
    cudaGetSymbolAddress(&p_xwf,   g_xwf);
    cudaGetSymbolAddress(&p_xwb,   g_xwb);
    cudaGetSymbolAddress(&p_qx,    g_qx);
    cudaGetSymbolAddress(&p_whd,   g_whd_t);
    cudaGetSymbolAddress(&p_wxo,   g_wxo_t);
    cudaGetSymbolAddress(&p_whfnk, g_whf_nk);
    cudaGetSymbolAddress(&p_whbnk, g_whb_nk);
    cudaGetSymbolAddress(&p_enc,   g_enc);
    cudaGetSymbolAddress(&p_encp,  g_encp);
    cudaGetSymbolAddress(&p_outs,  g_outs);
    cudaGetSymbolAddress(&p_SH,    g_stateH);
    cudaGetSymbolAddress(&p_SC,    g_stateC);
    cudaGetSymbolAddress(&p_lpart, g_lpart2);
    cudaGetSymbolAddress(&p_lcnt,  g_lbar_cnt);
    cudaGetSymbolAddress(&p_lgen,  g_lbar_genw);
    cudaGetSymbolAddress(&p_hd,    g_hd);
    float* hd0 = (float*)p_hd;
    float* hd1 = hd0 + BB * HH;

    cudaFuncSetAttribute(lstm_persist, cudaFuncAttributeMaxDynamicSharedMemorySize,
                         LSTM_SMEM_BYTES);

    zero_state_kernel<<<300, 256>>>();

    // all GEMMs direct from natural-layout weights (no transposes)
    gemm_tf32_bn<<<dim3(5, 200), 256>>>(W_emb, cw, emb_prj, nullptr,
                                        (float*)p_cemb, BB * CL, HH, EMB);
    gemm_tf32_bn<<<dim3(19, 200), 256>>>((float*)p_cemb, nullptr, Wx_f, b_f,
                                         (float*)p_xwf, BB * CL, 4 * HH, HH);    // ncu window
    gemm_tf32_bn<<<dim3(19, 200), 256>>>((float*)p_cemb, nullptr, Wx_b, b_b,
                                         (float*)p_xwb, BB * CL, 4 * HH, HH);
    gemm_tf32_bn<<<dim3(5, 15), 256>>>(W_emb, qw, emb_prj, nullptr,
                                       (float*)p_qemb, BB * QL, HH, EMB);
    gemm_tf32_bn<<<dim3(19, 15), 256>>>((float*)p_qemb, nullptr, Wx_d, b_d,
                                        (float*)p_qx, BB * QL, 4 * HH, HH);

    // LSTM/decoder gate reshuffles (layouts a GEMM can't produce)
    transpose_gates_nk<<<5625, 256>>>(Wh_f, (float*)p_whfnk);
    transpose_gates_nk<<<5625, 256>>>(Wh_b, (float*)p_whbnk);
    transpose_gates<<<1407, 256>>>(Wh_d, (float*)p_whd);
    transpose_gates<<<1407, 256>>>(Wx_d + HH * 4 * HH, (float*)p_wxo);

    // persistent BiLSTM (512 threads; ~3.5 ms measured)
    lstm_persist<<<LSTM_BLOCKS, LTHREADS, LSTM_SMEM_BYTES>>>(
        (const float*)p_whfnk, (const float*)p_whbnk,
        (const float*)p_xwf, (const float*)p_xwb,
        (float*)p_SH, (float*)p_SC, (float*)p_enc, (float*)p_lpart,
        (unsigned*)p_lcnt, (unsigned*)p_lgen);

    h0c0_kernel<<<75, 256>>>(Wh_init, Wc_init);
    gemm_tf32_bn<<<dim3(5, 200), 256>>>((float*)p_enc, nullptr, W_att, nullptr,
                                        (float*)p_encp, BB * CL, HH, 2 * HH);

    // decoder: per-step launches (graph edges do the sync)
    for (int t = 0; t < QL; t++) {
        const float* hin = (t & 1) ? hd1 : hd0;
        float* hout      = (t & 1) ? hd0 : hd1;
        dec_part<<<dim3(19, DKS), 256>>>(hin);
        dec_combine<<<75, 256>>>(hout, t);
        attn_score<<<BB, 512>>>(hout, cw);
        attn_ctx<<<dim3(5, BB), 256>>>();
        comb_part<<<dim3(5, CKS), 256>>>(hout, W_comb);
        comb_combine<<<75, 256>>>(t);
    }

    // vocab projection directly from W_gen[K][N]
    gemm_tf32_bn<<<dim3(391, 15), 256>>>((float*)p_outs, nullptr, W_gen, b_gen,
                                         out, BB * QL, VOC, HH);
    logsoftmax_kernel<<<BB * QL, 256>>>(out);
}

// round 17
// speedup vs baseline: 1.0754x; 1.0033x over previous
#include <cuda_runtime.h>
#include <math.h>

#define BB 32
#define CL 400
#define QL 30
#define HH 600
#define VOC 50000
#define EMB 300

#define LKS 6    // lstm k-split (kslice 100, padded to 112)
#define DKS 6    // decoder k-split (K=1200, kslice 200)
#define CKS 24   // comb k-split (K=1800, kslice 75)

#define LSTM_BLOCKS 120   // 10 n-tiles x LKS x 2 dirs
#define LTHREADS 512      // 16 warps

#define WS_STRIDE 116
#define WS_FLOATS (256 * WS_STRIDE)   // 29696
#define XC_FLOATS (32 * 260)          // 8320
#define LSTM_SMEM_BYTES ((WS_FLOATS + XC_FLOATS) * 4)   // 152064

// ---------------- scratch (device globals; allocation-free) ----------------
__device__ float g_cemb[BB*CL*HH];
__device__ float g_qemb[BB*QL*HH];
__device__ float g_xwf [BB*CL*4*HH];        // plain gate-blocked x-parts [row][g*600+j]
__device__ float g_xwb [BB*CL*4*HH];
__device__ float g_qx  [BB*QL*4*HH];
__device__ float g_whd_t[HH*HH*4];          // [k][j*4+g]
__device__ float g_wxo_t[HH*HH*4];
__device__ float g_whf_nk[4*HH*HH];         // [n=j*4+g][k]
__device__ float g_whb_nk[4*HH*HH];
__device__ float g_enc [BB*CL*2*HH];
__device__ float g_encp[BB*CL*HH];
__device__ float g_stateH[2*2*BB*HH];       // [dir][phase][b][j]
__device__ float g_stateC[2*BB*HH];
__device__ float g_hd[2][BB*HH];
__device__ float g_cd[BB*HH];
__device__ float g_oprev[BB*HH];
__device__ float g_alpha[BB*CL];
__device__ float g_a[BB*2*HH];
__device__ float g_outs[BB*QL*HH];
__device__ float g_lpart2[2*LKS*BB*4*HH];
__device__ float g_dpart[DKS*BB*4*HH];
__device__ float g_cpart[CKS*BB*HH];

// LSTM barrier: cnt and gen on separate 128B lines
__device__ __align__(128) unsigned g_lbar_cnt[32];
__device__ __align__(128) unsigned g_lbar_genw[32];

__device__ __forceinline__ void grid_sync_ptr(unsigned* cnt, volatile unsigned* gen, unsigned nb)
{
    __syncthreads();
    if (threadIdx.x == 0) {
        unsigned g = *gen;
        __threadfence();
        if (atomicAdd(cnt, 1u) == nb - 1u) {
            *cnt = 0u;
            __threadfence();
            *gen = g + 1u;
        } else {
            while (*gen == g) { }
            __threadfence();
        }
    }
    __syncthreads();
}

__device__ __forceinline__ float sigf(float x) { return 1.0f / (1.0f + expf(-x)); }

__device__ __forceinline__ float tf32r(float f)
{
    unsigned u; asm("cvt.rna.tf32.f32 %0, %1;" : "=r"(u) : "f"(f));
    return __uint_as_float(u);
}
__device__ __forceinline__ float4 tf32r4(float4 v)
{
    return make_float4(tf32r(v.x), tf32r(v.y), tf32r(v.z), tf32r(v.w));
}
__device__ __forceinline__ void mma8(float* d, const unsigned* a, const unsigned* b)
{
    asm volatile("mma.sync.aligned.m16n8k8.row.col.f32.tf32.tf32.f32 "
        "{%0,%1,%2,%3}, {%4,%5,%6,%7}, {%8,%9}, {%0,%1,%2,%3};"
        : "+f"(d[0]), "+f"(d[1]), "+f"(d[2]), "+f"(d[3])
        : "r"(a[0]), "r"(a[1]), "r"(a[2]), "r"(a[3]), "r"(b[0]), "r"(b[1]));
}

__device__ __forceinline__ unsigned smem_u32p(const void* p)
{
    return (unsigned)__cvta_generic_to_shared(p);
}
__device__ __forceinline__ void cpa16(unsigned dst, const void* src, int bytes)
{
    asm volatile("cp.async.cg.shared.global [%0], [%1], 16, %2;"
                 :: "r"(dst), "l"(src), "r"(bytes) : "memory");
}

// ---------------- tf32 GEMM (B natural layout, 3-stage cp.async) -----------
// C[M][N] = gather(X)[M][K] @ W[K][N]. W rows n-contiguous.
// Smem W tile [16][136] (conflict-free fragments). Requires N % 4 == 0.
__global__ void gemm_tf32_bn(const float* __restrict__ X, const int* __restrict__ gidx,
                             const float* __restrict__ W, const float* __restrict__ bias,
                             float* __restrict__ C, int M, int N, int K)
{
    __shared__ float smem[10368];   // Wk[3]:3x2176 (=6528), Xs[3]:3x1280 (=10368); Cs overlay
    float* WkB[3] = { smem, smem + 2176, smem + 4352 };
    float* XsB[3] = { smem + 6528, smem + 7808, smem + 9088 };
    const int tid = threadIdx.x;
    const int warp = tid >> 5, lane = tid & 31;
    const int lq = lane >> 2, lr = lane & 3;
    const int wn = (warp & 3) * 32, wm = (warp >> 2) * 32;
    const int bn0 = blockIdx.x * 128;
    const int bm0 = blockIdx.y * 64;

    const int wk0 = tid >> 5;               // k row 0..7
    const int wk1 = 8 + (tid >> 5);         // k row 8..15
    const int wn4 = (tid & 31) * 4;
    const int gw_n = bn0 + wn4;
    const int wvalid = (gw_n < N);          // N % 4 == 0: float4 all-in or all-out

    const int kqx = (tid & 3) * 4;
    const int m_x = tid >> 2;
    const float* rowX = nullptr;
    if (bm0 + m_x < M)
        rowX = X + (gidx ? (long)gidx[bm0 + m_x] * K : (long)(bm0 + m_x) * K);

    unsigned wka0[3], wka1[3], xsa[3];
#pragma unroll
    for (int b = 0; b < 3; b++) {
        wka0[b] = smem_u32p(&WkB[b][wk0 * 136 + wn4]);
        wka1[b] = smem_u32p(&WkB[b][wk1 * 136 + wn4]);
        xsa[b]  = smem_u32p(&XsB[b][m_x * 20 + kqx]);
    }

    const int KT = (K + 15) / 16;

#define GB_ISSUE(KT0, BUF) do {                                             \
        int kx_ = (KT0) * 16 + kqx;                                         \
        int bx_ = (rowX && kx_ < K) ? 16 : 0;                               \
        int kr0_ = (KT0) * 16 + wk0;                                        \
        int kr1_ = (KT0) * 16 + wk1;                                        \
        int b0_ = (wvalid && kr0_ < K) ? 16 : 0;                            \
        int b1_ = (wvalid && kr1_ < K) ? 16 : 0;                            \
        cpa16(wka0[BUF], b0_ ? W + (long)kr0_ * N + gw_n : W, b0_);         \
        cpa16(wka1[BUF], b1_ ? W + (long)kr1_ * N + gw_n : W, b1_);         \
        cpa16(xsa[BUF],  bx_ ? rowX + kx_ : W, bx_);                        \
        asm volatile("cp.async.commit_group;" ::: "memory");                \
    } while (0)

    float acc[2][4][4];
#pragma unroll
    for (int t = 0; t < 2; t++)
#pragma unroll
        for (int u = 0; u < 4; u++)
#pragma unroll
            for (int e = 0; e < 4; e++) acc[t][u][e] = 0.f;

    GB_ISSUE(0, 0);
    GB_ISSUE(1, 1);
    int buf = 0;
    for (int kt = 0; kt < KT; kt++) {
        if (kt + 2 < KT) {
            GB_ISSUE(kt + 2, (kt + 2) % 3);
            asm volatile("cp.async.wait_group 2;" ::: "memory");
        } else if (kt + 1 < KT) {
            asm volatile("cp.async.wait_group 1;" ::: "memory");
        } else {
            asm volatile("cp.async.wait_group 0;" ::: "memory");
        }
        __syncthreads();

        const float* Wk = WkB[buf];
        const float* Xs = XsB[buf];
#pragma unroll
        for (int kc = 0; kc < 2; kc++) {
            const int kb = kc * 8 + lr;
            unsigned a[2][4], b[4][2];
#pragma unroll
            for (int t = 0; t < 2; t++) {
                const float* p = Wk + kb * 136 + wn + t * 16 + lq;
                a[t][0] = __float_as_uint(p[0]);
                a[t][1] = __float_as_uint(p[8]);
                a[t][2] = __float_as_uint(p[4 * 136]);
                a[t][3] = __float_as_uint(p[4 * 136 + 8]);
            }
#pragma unroll
            for (int u = 0; u < 4; u++) {
                const float* p = Xs + (wm + u * 8 + lq) * 20 + kb;
                b[u][0] = __float_as_uint(p[0]);
                b[u][1] = __float_as_uint(p[4]);
            }
#pragma unroll
            for (int t = 0; t < 2; t++)
#pragma unroll
                for (int u = 0; u < 4; u++)
                    mma8(acc[t][u], a[t], b[u]);
        }
        __syncthreads();
        buf = (buf + 1 == 3) ? 0 : buf + 1;
    }
#undef GB_ISSUE

    float* Cs = smem;
#pragma unroll
    for (int t = 0; t < 2; t++)
#pragma unroll
        for (int u = 0; u < 4; u++) {
            int nl = wn + t * 16 + lq;
            int m = wm + u * 8 + lr * 2;
            Cs[m * 132 + nl]           = acc[t][u][0];
            Cs[(m + 1) * 132 + nl]     = acc[t][u][1];
            Cs[m * 132 + nl + 8]       = acc[t][u][2];
            Cs[(m + 1) * 132 + nl + 8] = acc[t][u][3];
        }
    __syncthreads();
#pragma unroll
    for (int l = 0; l < 8; l++) {
        int idx = tid + l * 256;
        int m = idx >> 5, nl4 = (idx & 31) * 4;
        int gm = bm0 + m, gn = bn0 + nl4;
        if (gm < M && gn < N) {
            float4 v = *(float4*)&Cs[m * 132 + nl4];
            if (bias) {
                v.x += bias[gn]; v.y += bias[gn + 1];
                v.z += bias[gn + 2]; v.w += bias[gn + 3];
            }
            *(float4*)(C + (long)gm * N + gn) = v;
        }
    }
}

// ---------------- small helpers ----------------
__global__ void zero_state_kernel()
{
    int i = blockIdx.x * 256 + threadIdx.x;
    if (i < 2 * 2 * BB * HH) g_stateH[i] = 0.f;
    if (i < 2 * BB * HH)     g_stateC[i] = 0.f;
    if (i < 32) { g_lbar_cnt[i] = 0u; g_lbar_genw[i] = 0u; }
}

__global__ void transpose_gates(const float* __restrict__ W, float* __restrict__ Wt)
{
    int idx = blockIdx.x * 256 + threadIdx.x;
    if (idx >= HH * HH) return;
    int k = idx / HH, j = idx % HH;
    float4 v;
    v.x = W[k * 4 * HH + j];
    v.y = W[k * 4 * HH + HH + j];
    v.z = W[k * 4 * HH + 2 * HH + j];
    v.w = W[k * 4 * HH + 3 * HH + j];
    ((float4*)Wt)[idx] = v;
}

__global__ void transpose_gates_nk(const float* __restrict__ W, float* __restrict__ out)
{
    long idx = (long)blockIdx.x * 256 + threadIdx.x;
    if (idx >= (long)4 * HH * HH) return;
    int n = (int)(idx / HH), k = (int)(idx % HH);
    out[idx] = W[(long)k * 4 * HH + (n & 3) * HH + (n >> 2)];
}

// ---------------- persistent BiLSTM: 512 threads, weights smem-resident -----
__global__ void lstm_persist(const float* __restrict__ Wf, const float* __restrict__ Wb,
                             const float* __restrict__ xf, const float* __restrict__ xb,
                             float* __restrict__ SH, float* __restrict__ SC,
                             float* __restrict__ enc, float* __restrict__ lpart,
                             unsigned* bcnt, unsigned* bgenw)
{
    extern __shared__ float dsm[];
    float* Ws = dsm;
    float* Xs = dsm + WS_FLOATS;
    float* Cs = dsm + WS_FLOATS;

    const int bx = blockIdx.x;
    const int tid = threadIdx.x;
    const int warp = tid >> 5, lane = tid & 31;
    const int lq = lane >> 2, lr = lane & 3;
    const int nb = bx % 10;
    const int ks = (bx / 10) % LKS;
    const int dir = bx / (10 * LKS);
    const int n0 = nb * 256;
    const int k0 = ks * 100;
    const int wn = warp * 16;
    const float* Wnk = dir ? Wb : Wf;
    float* outP = lpart + (long)(dir * LKS + ks) * BB * 4 * HH;
    volatile unsigned* bgen = (volatile unsigned*)bgenw;

    for (int idx4 = tid; idx4 < 256 * 29; idx4 += LTHREADS) {
        int n = idx4 / 29, kq = (idx4 % 29) * 4;
        float4 v = make_float4(0.f, 0.f, 0.f, 0.f);
        int gn = n0 + n;
        if (gn < 4 * HH && kq < 100)
            v = tf32r4(*(const float4*)(Wnk + (long)gn * HH + k0 + kq));
        *(float4*)&Ws[n * WS_STRIDE + kq] = v;
    }
    __syncthreads();

    for (int s = 0; s < CL; s++) {
        const int ph = s & 1;
        const float* H = SH + (long)(dir * 2 + ph) * BB * HH;

        for (int idx4 = tid; idx4 < 928; idx4 += LTHREADS) {
            int m = idx4 / 29, kq = (idx4 % 29) * 4;
            float4 v = make_float4(0.f, 0.f, 0.f, 0.f);
            if (kq < 100)
                v = tf32r4(*(const float4*)(H + (long)m * HH + k0 + kq));
            *(float4*)&Xs[m * WS_STRIDE + kq] = v;
        }
        __syncthreads();

        float acc[4][4];
#pragma unroll
        for (int u = 0; u < 4; u++)
#pragma unroll
            for (int e = 0; e < 4; e++) acc[u][e] = 0.f;

#pragma unroll
        for (int kt = 0; kt < 7; kt++) {
#pragma unroll
            for (int kc = 0; kc < 2; kc++) {
                const int kb = kt * 16 + kc * 8 + lr;
                unsigned a[4], b[4][2];
                const float* pa = Ws + (wn + lq) * WS_STRIDE + kb;
                a[0] = __float_as_uint(pa[0]);
                a[1] = __float_as_uint(pa[8 * WS_STRIDE]);
                a[2] = __float_as_uint(pa[4]);
                a[3] = __float_as_uint(pa[8 * WS_STRIDE + 4]);
#pragma unroll
                for (int u = 0; u < 4; u++) {
                    const float* pb = Xs + (u * 8 + lq) * WS_STRIDE + kb;
                    b[u][0] = __float_as_uint(pb[0]);
                    b[u][1] = __float_as_uint(pb[4]);
                }
#pragma unroll
                for (int u = 0; u < 4; u++)
                    mma8(acc[u], a, b[u]);
            }
        }
        __syncthreads();

#pragma unroll
        for (int u = 0; u < 4; u++) {
            int nl = wn + lq;
            int m = u * 8 + lr * 2;
            Cs[m * 260 + nl]           = acc[u][0];
            Cs[(m + 1) * 260 + nl]     = acc[u][1];
            Cs[m * 260 + nl + 8]       = acc[u][2];
            Cs[(m + 1) * 260 + nl + 8] = acc[u][3];
        }
        __syncthreads();
#pragma unroll
        for (int l = 0; l < 4; l++) {
            int idx = tid + l * LTHREADS;
            int m = idx >> 6, nl4 = (idx & 63) * 4;
            if (n0 + nl4 < 4 * HH)
                *(float4*)(outP + (long)m * 4 * HH + n0 + nl4) = *(float4*)&Cs[m * 260 + nl4];
        }
        grid_sync_ptr(bcnt, bgen, LSTM_BLOCKS);

        for (int idx = bx * LTHREADS + tid; idx < 2 * BB * HH; idx += LSTM_BLOCKS * LTHREADS) {
            const int d2 = idx / (BB * HH);
            const int r2 = idx % (BB * HH);
            const int b = r2 / HH, j = r2 % HH;
            const int tt = d2 ? (CL - 1 - s) : s;
            float4 g4 = make_float4(0.f, 0.f, 0.f, 0.f);
#pragma unroll
            for (int kq = 0; kq < LKS; kq++) {
                const float4* P = (const float4*)(lpart + ((long)(d2 * LKS + kq) * BB + b) * 4 * HH);
                float4 p = P[j];
                g4.x += p.x; g4.y += p.y; g4.z += p.z; g4.w += p.w;
            }
            const float* xw = d2 ? xb : xf;
            const long xbs = ((long)b * CL + tt) * 4 * HH;
            float gi = g4.x + xw[xbs + j];
            float gf = g4.y + xw[xbs + HH + j];
            float gg = g4.z + xw[xbs + 2 * HH + j];
            float go = g4.w + xw[xbs + 3 * HH + j];
            float c = SC[(long)d2 * BB * HH + b * HH + j];
            c = sigf(gf) * c + sigf(gi) * tanhf(gg);
            float h = sigf(go) * tanhf(c);
            SC[(long)d2 * BB * HH + b * HH + j] = c;
            SH[(long)(d2 * 2 + (ph ^ 1)) * BB * HH + b * HH + j] = h;
            enc[((long)b * CL + tt) * 2 * HH + d2 * HH + j] = h;
        }
        grid_sync_ptr(bcnt, bgen, LSTM_BLOCKS);
    }
}

// ======= M=32 partial fp32 GEMM tile =======
#define PART_TILE(LOAD_A, LOAD_B, KSLICE, NTOT)                                     \
    {                                                                               \
        float acc[4][4];                                                            \
        _Pragma("unroll") for (int r = 0; r < 4; r++)                               \
        _Pragma("unroll") for (int g = 0; g < 4; g++) acc[r][g] = 0.f;              \
        for (int kt = 0; kt < (KSLICE); kt += 16) {                                 \
            _Pragma("unroll") for (int l = 0; l < 2; l++) {                         \
                int idx = tid + l * 256;                                            \
                int kk = idx >> 5; int nn = (idx & 31) * 4;                         \
                float4 v = make_float4(0.f, 0.f, 0.f, 0.f);                         \
                int kl = kt + kk;                                                   \
                if (kl < (KSLICE) && (n0 + nn) < (NTOT)) { int kg = k0 + kl; LOAD_B; } \
                *(float4*)&Bs[kk][nn] = v;                                          \
            }                                                                       \
            _Pragma("unroll") for (int l = 0; l < 2; l++) {                         \
                int idx = tid + l * 256;                                            \
                int r = idx >> 4; int kk = idx & 15;                                \
                float v = 0.f;                                                      \
                int kl = kt + kk;                                                   \
                if (kl < (KSLICE)) { int kg = k0 + kl; LOAD_A; }                    \
                As[r][kk] = v;                                                      \
            }                                                                       \
            __syncthreads();                                                        \
            _Pragma("unroll") for (int kq = 0; kq < 4; kq++) {                      \
                float4 a4[4];                                                       \
                _Pragma("unroll") for (int r = 0; r < 4; r++)                       \
                    a4[r] = *(const float4*)&As[ty * 4 + r][kq * 4];                \
                _Pragma("unroll") for (int kk = 0; kk < 4; kk++) {                  \
                    float4 b4 = *(const float4*)&Bs[kq * 4 + kk][tx * 4];           \
                    _Pragma("unroll") for (int r = 0; r < 4; r++) {                 \
                        float a = (kk == 0) ? a4[r].x : (kk == 1) ? a4[r].y         \
                                  : (kk == 2) ? a4[r].z : a4[r].w;                  \
                        acc[r][0] += a * b4.x; acc[r][1] += a * b4.y;               \
                        acc[r][2] += a * b4.z; acc[r][3] += a * b4.w;               \
                    }                                                               \
                }                                                                   \
            }                                                                       \
            __syncthreads();                                                        \
        }                                                                           \
        int nn = n0 + tx * 4;                                                       \
        if (nn < (NTOT)) {                                                          \
            _Pragma("unroll") for (int r = 0; r < 4; r++)                           \
                *(float4*)(outp + (long)(ty * 4 + r) * (NTOT) + nn) =               \
                    make_float4(acc[r][0], acc[r][1], acc[r][2], acc[r][3]);        \
        }                                                                           \
    }

// ---------------- decoder step kernels (per-step launches) ----------------
__global__ void dec_part(const float* __restrict__ hdin)
{
    __shared__ float Bs[16][128];
    __shared__ float As[32][16];
    const int tid = threadIdx.x;
    const int tx = tid & 31, ty = tid >> 5;
    const int jt = blockIdx.x, ks = blockIdx.y;
    const int n0 = jt * 128;
    const int k0 = ks * 200;
    float* outp = g_dpart + (long)ks * BB * 4 * HH;
    PART_TILE(v = (kg < HH) ? g_oprev[r * HH + kg] : hdin[r * HH + kg - HH],
              v = (kg < HH) ? *(const float4*)(g_wxo_t + (long)kg * 4 * HH + n0 + nn)
                            : *(const float4*)(g_whd_t + (long)(kg - HH) * 4 * HH + n0 + nn),
              200, 4 * HH)
}

__global__ void dec_combine(float* __restrict__ hdout, int t)
{
    int idx = blockIdx.x * 256 + threadIdx.x;
    if (idx >= BB * HH) return;
    const int b = idx / HH, j = idx % HH;
    const float4* P = (const float4*)g_dpart;
    float4 g4 = P[(long)b * HH + j];
#pragma unroll
    for (int kq = 1; kq < DKS; kq++) {
        float4 p = P[((long)kq * BB + b) * HH + j];
        g4.x += p.x; g4.y += p.y; g4.z += p.z; g4.w += p.w;
    }
    const long xb = ((long)b * QL + t) * 4 * HH;
    float gi = g4.x + g_qx[xb + j];
    float gf = g4.y + g_qx[xb + HH + j];
    float gg = g4.z + g_qx[xb + 2 * HH + j];
    float go = g4.w + g_qx[xb + 3 * HH + j];
    float c = g_cd[b * HH + j];
    c = sigf(gf) * c + sigf(gi) * tanhf(gg);
    g_cd[b * HH + j] = c;
    hdout[b * HH + j] = sigf(go) * tanhf(c);
}

// scores + masked softmax -> g_alpha[b][c]  (512 threads = 16 warps)
__global__ void attn_score(const float* __restrict__ hd, const int* __restrict__ cw)
{
    const int b = blockIdx.x;
    const int tid = threadIdx.x;
    __shared__ float sh_h[HH];
    __shared__ float sh_e[CL];
    __shared__ float sred[16];
    const int warp = tid >> 5, lane = tid & 31;

    for (int i = tid; i < HH; i += 512) sh_h[i] = hd[b * HH + i];
    __syncthreads();
    for (int c = warp; c < CL; c += 16) {
        const float* ep = g_encp + ((long)b * CL + c) * HH;
        float s = 0.f;
        for (int k = lane; k < HH; k += 32) s += sh_h[k] * ep[k];
        for (int o = 16; o; o >>= 1) s += __shfl_down_sync(0xffffffffu, s, o);
        if (!lane) sh_e[c] = (cw[b * CL + c] != 0) ? s : -1e30f;
    }
    __syncthreads();

    float m = -1e30f;
    for (int c = tid; c < CL; c += 512) m = fmaxf(m, sh_e[c]);
    for (int o = 16; o; o >>= 1) m = fmaxf(m, __shfl_xor_sync(0xffffffffu, m, o));
    if (!lane) sred[warp] = m;
    __syncthreads();
    if (tid == 0) {
        float v = sred[0];
        for (int w = 1; w < 16; w++) v = fmaxf(v, sred[w]);
        sred[0] = v;
    }
    __syncthreads();
    m = sred[0];
    __syncthreads();

    float s = 0.f;
    for (int c = tid; c < CL; c += 512) {
        float e = expf(sh_e[c] - m);
        sh_e[c] = e;
        s += e;
    }
    for (int o = 16; o; o >>= 1) s += __shfl_xor_sync(0xffffffffu, s, o);
    if (!lane) sred[warp] = s;
    __syncthreads();
    if (tid == 0) {
        float v = 0.f;
        for (int w = 0; w < 16; w++) v += sred[w];
        sred[0] = v;
    }
    __syncthreads();
    const float inv = 1.0f / sred[0];
    for (int c = tid; c < CL; c += 512)
        g_alpha[b * CL + c] = sh_e[c] * inv;
}

__global__ void attn_ctx()
{
    const int b = blockIdx.y;
    const int d = blockIdx.x * 256 + threadIdx.x;
    __shared__ float sal[CL];
    for (int c = threadIdx.x; c < CL; c += 256) sal[c] = g_alpha[b * CL + c];
    __syncthreads();
    if (d >= 2 * HH) return;
    const float* eb = g_enc + (long)b * CL * 2 * HH + d;
    float acc = 0.f;
#pragma unroll 8
    for (int c = 0; c < CL; c++) acc += sal[c] * eb[(long)c * 2 * HH];
    g_a[b * 2 * HH + d] = acc;
}

__global__ void comb_part(const float* __restrict__ hdnew, const float* __restrict__ Wcomb)
{
    __shared__ float Bs[16][128];
    __shared__ float As[32][16];
    const int tid = threadIdx.x;
    const int tx = tid & 31, ty = tid >> 5;
    const int jt = blockIdx.x, ks = blockIdx.y;
    const int n0 = jt * 128;
    const int k0 = ks * 75;
    float* outp = g_cpart + (long)ks * BB * HH;
    PART_TILE(v = (kg < HH) ? hdnew[r * HH + kg] : g_a[r * 2 * HH + kg - HH],
              v = *(const float4*)(Wcomb + (long)kg * HH + n0 + nn),
              75, HH)
}

__global__ void comb_combine(int t)
{
    int idx = blockIdx.x * 256 + threadIdx.x;
    if (idx >= BB * HH) return;
    const int b = idx / HH, j = idx % HH;
    float s = 0.f;
#pragma unroll
    for (int kq = 0; kq < CKS; kq++) s += g_cpart[((long)kq * BB + b) * HH + j];
    float O = tanhf(s);
    g_oprev[b * HH + j] = O;
    g_outs[((long)b * QL + t) * HH + j] = O;
}

// ---------------- h0/c0 projection + o_prev init ----------------
__global__ void h0c0_kernel(const float* __restrict__ Whi, const float* __restrict__ Wci)
{
    int idx = blockIdx.x * 256 + threadIdx.x;
    if (idx >= BB * HH) return;
    int b = idx / HH, j = idx % HH;
    const float* hf = g_stateH + 0 * BB * HH;
    const float* hb = g_stateH + 2 * BB * HH;
    const float* cf = g_stateC;
    const float* cb = g_stateC + BB * HH;
    float ah = 0.f, ac = 0.f;
    for (int k = 0; k < HH; k++) {
        ah += hf[b * HH + k] * Whi[k * HH + j];
        ac += cf[b * HH + k] * Wci[k * HH + j];
    }
    for (int k = 0; k < HH; k++) {
        ah += hb[b * HH + k] * Whi[(HH + k) * HH + j];
        ac += cb[b * HH + k] * Wci[(HH + k) * HH + j];
    }
    g_hd[0][idx] = ah;
    g_cd[idx] = ac;
    g_oprev[idx] = 0.f;
}

// ---------------- log-softmax over vocab, in place (512 thr, float4) --------
__global__ void logsoftmax_kernel(float* __restrict__ x)
{
    const long base = (long)blockIdx.x * VOC;
    const int tid = threadIdx.x;
    __shared__ float sred[16];
    const int warp = tid >> 5, lane = tid & 31;
    float4* x4 = (float4*)(x + base);
    const int N4 = VOC / 4;   // 12500

    float m = -1e30f;
    for (int i = tid; i < N4; i += 512) {
        float4 v = x4[i];
        m = fmaxf(m, fmaxf(fmaxf(v.x, v.y), fmaxf(v.z, v.w)));
    }
    for (int o = 16; o; o >>= 1) m = fmaxf(m, __shfl_xor_sync(0xffffffffu, m, o));
    if (!lane) sred[warp] = m;
    __syncthreads();
    if (tid == 0) {
        float v = sred[0];
        for (int w = 1; w < 16; w++) v = fmaxf(v, sred[w]);
        sred[0] = v;
    }
    __syncthreads();
    m = sred[0];
    __syncthreads();

    float s = 0.f;
    for (int i = tid; i < N4; i += 512) {
        float4 v = x4[i];
        s += expf(v.x - m) + expf(v.y - m) + expf(v.z - m) + expf(v.w - m);
    }
    for (int o = 16; o; o >>= 1) s += __shfl_xor_sync(0xffffffffu, s, o);
    if (!lane) sred[warp] = s;
    __syncthreads();
    if (tid == 0) {
        float v = 0.f;
        for (int w = 0; w < 16; w++) v += sred[w];
        sred[0] = v;
    }
    __syncthreads();
    const float lse = m + logf(sred[0]);

    for (int i = tid; i < N4; i += 512) {
        float4 v = x4[i];
        v.x -= lse; v.y -= lse; v.z -= lse; v.w -= lse;
        x4[i] = v;
    }
}

// ---------------- launch ----------------
extern "C" void kernel_launch(void* const* d_in, const int* in_sizes, int n_in,
                              void* d_out, int out_size)
{
    (void)in_sizes; (void)n_in; (void)out_size;
    const int*   cw      = (const int*)  d_in[0];
    const int*   qw      = (const int*)  d_in[1];
    const float* W_emb   = (const float*)d_in[2];
    const float* emb_prj = (const float*)d_in[3];
    const float* Wx_f    = (const float*)d_in[4];
    const float* Wh_f    = (const float*)d_in[5];
    const float* b_f     = (const float*)d_in[6];
    const float* Wx_b    = (const float*)d_in[7];
    const float* Wh_b    = (const float*)d_in[8];
    const float* b_b     = (const float*)d_in[9];
    const float* Wh_init = (const float*)d_in[10];
    const float* Wc_init = (const float*)d_in[11];
    const float* Wx_d    = (const float*)d_in[12];
    const float* Wh_d    = (const float*)d_in[13];
    const float* b_d     = (const float*)d_in[14];
    const float* W_att   = (const float*)d_in[15];
    const float* W_comb  = (const float*)d_in[16];
    const float* W_gen   = (const float*)d_in[17];
    const float* b_gen   = (const float*)d_in[18];
    float* out = (float*)d_out;

    void *p_cemb, *p_qemb, *p_xwf, *p_xwb, *p_qx;
    void *p_whd, *p_wxo, *p_whfnk, *p_whbnk;
    void *p_enc, *p_encp, *p_outs, *p_SH, *p_SC, *p_lpart;
    void *p_lcnt, *p_lgen, *p_hd;
    cudaGetSymbolAddress(&p_cemb,  g_cemb);
    cudaGetSymbolAddress(&p_qemb,  g_qemb);
    cudaGetSymbolAddress(&p_xwf,   g_xwf);
    cudaGetSymbolAddress(&p_xwb,   g_xwb);
    cudaGetSymbolAddress(&p_qx,    g_qx);
    cudaGetSymbolAddress(&p_whd,   g_whd_t);
    cudaGetSymbolAddress(&p_wxo,   g_wxo_t);
    cudaGetSymbolAddress(&p_whfnk, g_whf_nk);
    cudaGetSymbolAddress(&p_whbnk, g_whb_nk);
    cudaGetSymbolAddress(&p_enc,   g_enc);
    cudaGetSymbolAddress(&p_encp,  g_encp);
    cudaGetSymbolAddress(&p_outs,  g_outs);
    cudaGetSymbolAddress(&p_SH,    g_stateH);
    cudaGetSymbolAddress(&p_SC,    g_stateC);
    cudaGetSymbolAddress(&p_lpart, g_lpart2);
    cudaGetSymbolAddress(&p_lcnt,  g_lbar_cnt);
    cudaGetSymbolAddress(&p_lgen,  g_lbar_genw);
    cudaGetSymbolAddress(&p_hd,    g_hd);
    float* hd0 = (float*)p_hd;
    float* hd1 = hd0 + BB * HH;

    cudaFuncSetAttribute(lstm_persist, cudaFuncAttributeMaxDynamicSharedMemorySize,
                         LSTM_SMEM_BYTES);

    zero_state_kernel<<<300, 256>>>();

    // all GEMMs direct from natural-layout weights (no transposes)
    gemm_tf32_bn<<<dim3(5, 200), 256>>>(W_emb, cw, emb_prj, nullptr,
                                        (float*)p_cemb, BB * CL, HH, EMB);
    gemm_tf32_bn<<<dim3(19, 200), 256>>>((float*)p_cemb, nullptr, Wx_f, b_f,
                                         (float*)p_xwf, BB * CL, 4 * HH, HH);    // ncu window
    gemm_tf32_bn<<<dim3(19, 200), 256>>>((float*)p_cemb, nullptr, Wx_b, b_b,
                                         (float*)p_xwb, BB * CL, 4 * HH, HH);
    gemm_tf32_bn<<<dim3(5, 15), 256>>>(W_emb, qw, emb_prj, nullptr,
                                       (float*)p_qemb, BB * QL, HH, EMB);
    gemm_tf32_bn<<<dim3(19, 15), 256>>>((float*)p_qemb, nullptr, Wx_d, b_d,
                                        (float*)p_qx, BB * QL, 4 * HH, HH);

    // LSTM/decoder gate reshuffles (layouts a GEMM can't produce)
    transpose_gates_nk<<<5625, 256>>>(Wh_f, (float*)p_whfnk);
    transpose_gates_nk<<<5625, 256>>>(Wh_b, (float*)p_whbnk);
    transpose_gates<<<1407, 256>>>(Wh_d, (float*)p_whd);
    transpose_gates<<<1407, 256>>>(Wx_d + HH * 4 * HH, (float*)p_wxo);

    // persistent BiLSTM (512 threads; ~3.5 ms measured)
    lstm_persist<<<LSTM_BLOCKS, LTHREADS, LSTM_SMEM_BYTES>>>(
        (const float*)p_whfnk, (const float*)p_whbnk,
        (const float*)p_xwf, (const float*)p_xwb,
        (float*)p_SH, (float*)p_SC, (float*)p_enc, (float*)p_lpart,
        (unsigned*)p_lcnt, (unsigned*)p_lgen);

    h0c0_kernel<<<75, 256>>>(Wh_init, Wc_init);
    gemm_tf32_bn<<<dim3(5, 200), 256>>>((float*)p_enc, nullptr, W_att, nullptr,
                                        (float*)p_encp, BB * CL, HH, 2 * HH);

    // decoder: per-step launches (graph edges do the sync)
    for (int t = 0; t < QL; t++) {
        const float* hin = (t & 1) ? hd1 : hd0;
        float* hout      = (t & 1) ? hd0 : hd1;
        dec_part<<<dim3(19, DKS), 256>>>(hin);
        dec_combine<<<75, 256>>>(hout, t);
        attn_score<<<BB, 512>>>(hout, cw);
        attn_ctx<<<dim3(5, BB), 256>>>();
        comb_part<<<dim3(5, CKS), 256>>>(hout, W_comb);
        comb_combine<<<75, 256>>>(t);
    }

    // vocab projection directly from W_gen[K][N]
    gemm_tf32_bn<<<dim3(391, 15), 256>>>((float*)p_outs, nullptr, W_gen, b_gen,
                                         out, BB * QL, VOC, HH);
    logsoftmax_kernel<<<BB * QL, 512>>>(out);
}